// round 4
// baseline (speedup 1.0000x reference)
#include <cuda_runtime.h>

#define NN 50000
#define EE 640000
#define QS 1024          // row stride of fused qkv/skip buffer

// ---- scratch (static device globals: allocation-free rule) ----
__device__ __align__(16) float g_buf[(size_t)NN * QS];   // [q|k|v|x_r] per node, 204.8MB
__device__ __align__(16) float g_h[(size_t)NN * 256];    // post-LN hidden, 51.2MB
__device__ int g_degcur[2 * NN];                          // [deg | cursor], one memset
__device__ int g_start[NN + 1];
__device__ int g_esrc[EE];

// ---- packed f32x2 helpers ----
#define PACK2(p, lo, hi)   asm("mov.b64 %0, {%1,%2};" : "=l"(p) : "f"(lo), "f"(hi))
#define BCAST2(p, v)       asm("mov.b64 %0, {%1,%1};" : "=l"(p) : "f"(v))
#define UNPACK2(lo, hi, p) asm("mov.b64 {%0,%1}, %2;" : "=f"(lo), "=f"(hi) : "l"(p))
#define FMA2(d, a, b, c)   asm("fma.rn.f32x2 %0, %1, %2, %3;" : "=l"(d) : "l"(a), "l"(b), "l"(c))

// ============================================================================
// Kernel 1: fused QKV+skip GEMM.  out[n, 1024] = x[n,64] @ [Wq|Wk|Wv|Wskip]^T + b
// ============================================================================
__global__ __launch_bounds__(256) void gemm_qkvs(
    const float* __restrict__ x,
    const float* __restrict__ Wq, const float* __restrict__ bq,
    const float* __restrict__ Wk, const float* __restrict__ bk,
    const float* __restrict__ Wv, const float* __restrict__ bv,
    const float* __restrict__ Wsk, const float* __restrict__ bsk)
{
    __shared__ float Xs[32 * 128];   // [k][r]
    __shared__ float Wsh[32 * 128];  // [k][j]

    int t = threadIdx.x;
    int bx = blockIdx.x;             // col tile (0..7)
    int by = blockIdx.y;             // row tile (0..390)
    int c0 = bx * 128;
    int which = c0 >> 8;
    int dbase = c0 & 255;
    const float* W = (which == 0) ? Wq : (which == 1) ? Wk : (which == 2) ? Wv : Wsk;
    const float* B = (which == 0) ? bq : (which == 1) ? bk : (which == 2) ? bv : bsk;
    int row0 = by * 128;

    int tx = t & 15, ty = t >> 4;
    unsigned long long acc[8][4];
#pragma unroll
    for (int i = 0; i < 8; i++)
#pragma unroll
        for (int j = 0; j < 4; j++) acc[i][j] = 0ull;

    for (int kc = 0; kc < 64; kc += 32) {
        __syncthreads();
#pragma unroll
        for (int i = 0; i < 4; i++) {
            int u = t + i * 256;
            int r = u >> 3, kq = u & 7;
            int rg = row0 + r;
            float4 v = make_float4(0.f, 0.f, 0.f, 0.f);
            if (rg < NN) v = *(const float4*)(x + (size_t)rg * 64 + kc + kq * 4);
            Xs[(kq * 4 + 0) * 128 + r] = v.x;
            Xs[(kq * 4 + 1) * 128 + r] = v.y;
            Xs[(kq * 4 + 2) * 128 + r] = v.z;
            Xs[(kq * 4 + 3) * 128 + r] = v.w;
        }
#pragma unroll
        for (int i = 0; i < 4; i++) {
            int u = t + i * 256;
            int j = u >> 3, kq = u & 7;
            float4 v = *(const float4*)(W + (size_t)(dbase + j) * 64 + kc + kq * 4);
            Wsh[(kq * 4 + 0) * 128 + j] = v.x;
            Wsh[(kq * 4 + 1) * 128 + j] = v.y;
            Wsh[(kq * 4 + 2) * 128 + j] = v.z;
            Wsh[(kq * 4 + 3) * 128 + j] = v.w;
        }
        __syncthreads();
#pragma unroll
        for (int k = 0; k < 32; k++) {
            float a[8];
            *(float4*)(a)     = *(const float4*)&Xs[k * 128 + ty * 8];
            *(float4*)(a + 4) = *(const float4*)&Xs[k * 128 + ty * 8 + 4];
            float4 b0 = *(const float4*)&Wsh[k * 128 + tx * 8];
            float4 b1 = *(const float4*)&Wsh[k * 128 + tx * 8 + 4];
            unsigned long long bp[4];
            PACK2(bp[0], b0.x, b0.y);
            PACK2(bp[1], b0.z, b0.w);
            PACK2(bp[2], b1.x, b1.y);
            PACK2(bp[3], b1.z, b1.w);
#pragma unroll
            for (int i = 0; i < 8; i++) {
                unsigned long long ap;
                BCAST2(ap, a[i]);
#pragma unroll
                for (int j = 0; j < 4; j++) FMA2(acc[i][j], ap, bp[j], acc[i][j]);
            }
        }
    }
    float bj[8];
#pragma unroll
    for (int j = 0; j < 8; j++) bj[j] = B[dbase + tx * 8 + j];
#pragma unroll
    for (int i = 0; i < 8; i++) {
        int rg = row0 + ty * 8 + i;
        if (rg >= NN) continue;
        float* op = g_buf + (size_t)rg * QS + c0 + tx * 8;
        float c[8];
#pragma unroll
        for (int j = 0; j < 4; j++) UNPACK2(c[2 * j], c[2 * j + 1], acc[i][j]);
        float4 o0, o1;
        o0.x = c[0] + bj[0]; o0.y = c[1] + bj[1];
        o0.z = c[2] + bj[2]; o0.w = c[3] + bj[3];
        o1.x = c[4] + bj[4]; o1.y = c[5] + bj[5];
        o1.z = c[6] + bj[6]; o1.w = c[7] + bj[7];
        *(float4*)(op)     = o0;
        *(float4*)(op + 4) = o1;
    }
}

// ============================================================================
// CSR build: histogram -> exclusive scan (single block) -> scatter
// ============================================================================
__global__ __launch_bounds__(256) void hist_kernel(const int* __restrict__ ei)
{
    int e = blockIdx.x * 256 + threadIdx.x;
    if (e < EE) atomicAdd(&g_degcur[ei[EE + e]], 1);
}

__global__ __launch_bounds__(1024) void scan_kernel()
{
    __shared__ int wsum[32];
    __shared__ int carryS;
    int t = threadIdx.x;
    int lane = t & 31, w = t >> 5;
    if (t == 0) carryS = 0;
    __syncthreads();
    for (int base = 0; base < NN; base += 1024) {
        int i = base + t;
        int v = (i < NN) ? g_degcur[i] : 0;
        int xv = v;
#pragma unroll
        for (int off = 1; off < 32; off <<= 1) {
            int u = __shfl_up_sync(0xffffffffu, xv, off);
            if (lane >= off) xv += u;
        }
        if (lane == 31) wsum[w] = xv;
        __syncthreads();
        if (w == 0) {
            int y = wsum[lane];
#pragma unroll
            for (int off = 1; off < 32; off <<= 1) {
                int u = __shfl_up_sync(0xffffffffu, y, off);
                if (lane >= off) y += u;
            }
            wsum[lane] = y;
        }
        __syncthreads();
        int incl = xv + (w ? wsum[w - 1] : 0);
        int c = carryS;
        if (i < NN) g_start[i] = c + incl - v;
        __syncthreads();
        if (t == 0) carryS = c + wsum[31];
        __syncthreads();
    }
    if (t == 0) g_start[NN] = carryS;
}

__global__ __launch_bounds__(256) void scatter_kernel(const int* __restrict__ ei)
{
    int e = blockIdx.x * 256 + threadIdx.x;
    if (e < EE) {
        int d = ei[EE + e];
        int s = ei[e];
        int pos = g_start[d] + atomicAdd(&g_degcur[NN + d], 1);
        g_esrc[pos] = s;
    }
}

// ============================================================================
// Kernel 3: warp-per-dst online-softmax attention + beta-gate + LN.
// Register double-buffered k/v gathers: edge e+1's loads issue before edge e's
// compute chain, giving each LDG a full iteration of latency lead.
// ============================================================================
__global__ __launch_bounds__(256) void attn_kernel(
    const float* __restrict__ Wbeta,
    const float* __restrict__ lng, const float* __restrict__ lnb)
{
    __shared__ float sWb[768];
    __shared__ float sg[256], sb[256];
    int t = threadIdx.x;
    for (int i = t; i < 768; i += 256) sWb[i] = Wbeta[i];
    if (t < 256) { sg[t] = lng[t]; sb[t] = lnb[t]; }
    __syncthreads();

    int warp = t >> 5, lane = t & 31;
    int node = blockIdx.x * 8 + warp;
    if (node >= NN) return;

    int c0 = lane * 8;
    const float* qp = g_buf + (size_t)node * QS + c0;
    float q[8];
    *(float4*)(q)     = *(const float4*)(qp);
    *(float4*)(q + 4) = *(const float4*)(qp + 4);
#pragma unroll
    for (int u = 0; u < 8; u++) q[u] *= 0.125f;   // 1/sqrt(64)

    // x_r load issued early, consumed after the loop
    const float* xp = g_buf + (size_t)node * QS + 768 + c0;
    float4 xra = *(const float4*)(xp);
    float4 xrb = *(const float4*)(xp + 4);

    float m = -1e30f, ssum = 0.f;
    float acc[8];
#pragma unroll
    for (int u = 0; u < 8; u++) acc[u] = 0.f;

    int e0 = g_start[node], e1 = g_start[node + 1];

    // ---- stage 0: preload edge e0 ----
    float4 ka, kb, va, vb;
    int src1 = 0;
    if (e0 < e1) {
        int src0 = g_esrc[e0];
        const float* kp = g_buf + (size_t)src0 * QS + 256 + c0;
        ka = *(const float4*)(kp);
        kb = *(const float4*)(kp + 4);
        va = *(const float4*)(kp + 256);
        vb = *(const float4*)(kp + 260);
        src1 = (e0 + 1 < e1) ? g_esrc[e0 + 1] : 0;
    }

    for (int e = e0; e < e1; e++) {
        // prefetch edge e+1 while computing edge e
        float4 nka, nkb, nva, nvb;
        int src2 = 0;
        bool more = (e + 1 < e1);
        if (more) {
            const float* kp = g_buf + (size_t)src1 * QS + 256 + c0;
            nka = *(const float4*)(kp);
            nkb = *(const float4*)(kp + 4);
            nva = *(const float4*)(kp + 256);
            nvb = *(const float4*)(kp + 260);
            src2 = (e + 2 < e1) ? g_esrc[e + 2] : 0;
        }

        float p = q[0] * ka.x + q[1] * ka.y + q[2] * ka.z + q[3] * ka.w
                + q[4] * kb.x + q[5] * kb.y + q[6] * kb.z + q[7] * kb.w;
        p += __shfl_xor_sync(0xffffffffu, p, 1, 8);
        p += __shfl_xor_sync(0xffffffffu, p, 2, 8);
        p += __shfl_xor_sync(0xffffffffu, p, 4, 8);
        float mn = fmaxf(m, p);
        float sc = __expf(m - mn);
        float wgt = __expf(p - mn);
        m = mn;
        ssum = ssum * sc + wgt;
        acc[0] = acc[0] * sc + wgt * va.x;
        acc[1] = acc[1] * sc + wgt * va.y;
        acc[2] = acc[2] * sc + wgt * va.z;
        acc[3] = acc[3] * sc + wgt * va.w;
        acc[4] = acc[4] * sc + wgt * vb.x;
        acc[5] = acc[5] * sc + wgt * vb.y;
        acc[6] = acc[6] * sc + wgt * vb.z;
        acc[7] = acc[7] * sc + wgt * vb.w;

        if (more) { ka = nka; kb = nkb; va = nva; vb = nvb; src1 = src2; }
    }
    float inv = 1.f / (ssum + 1e-16f);
    float outv[8];
#pragma unroll
    for (int u = 0; u < 8; u++) outv[u] = acc[u] * inv;

    float xr[8];
    xr[0] = xra.x; xr[1] = xra.y; xr[2] = xra.z; xr[3] = xra.w;
    xr[4] = xrb.x; xr[5] = xrb.y; xr[6] = xrb.z; xr[7] = xrb.w;

    // beta = sigmoid( [out, x_r, out - x_r] . Wbeta )
    float part = 0.f;
#pragma unroll
    for (int u = 0; u < 8; u++) {
        int c = c0 + u;
        part += outv[u] * sWb[c] + xr[u] * sWb[256 + c] + (outv[u] - xr[u]) * sWb[512 + c];
    }
#pragma unroll
    for (int off = 16; off > 0; off >>= 1)
        part += __shfl_xor_sync(0xffffffffu, part, off);
    float beta = 1.f / (1.f + __expf(-part));

    float h[8], sum = 0.f, sq = 0.f;
#pragma unroll
    for (int u = 0; u < 8; u++) {
        h[u] = beta * xr[u] + (1.f - beta) * outv[u];
        sum += h[u];
        sq += h[u] * h[u];
    }
#pragma unroll
    for (int off = 16; off > 0; off >>= 1) {
        sum += __shfl_xor_sync(0xffffffffu, sum, off);
        sq  += __shfl_xor_sync(0xffffffffu, sq, off);
    }
    float mu = sum * (1.f / 256.f);
    float var = sq * (1.f / 256.f) - mu * mu;
    float rstd = rsqrtf(var + 1e-5f);

    float o[8];
#pragma unroll
    for (int u = 0; u < 8; u++) {
        int c = c0 + u;
        o[u] = (h[u] - mu) * rstd * sg[c] + sb[c];
    }
    float* hp = g_h + (size_t)node * 256 + c0;
    *(float4*)(hp)     = *(const float4*)(o);
    *(float4*)(hp + 4) = *(const float4*)(o + 4);
}

// ============================================================================
// Kernel 4: proj GEMM + bias + residual + ReLU.
// ============================================================================
__global__ __launch_bounds__(256) void gemm_proj(
    const float* __restrict__ x,
    const float* __restrict__ Wp, const float* __restrict__ bp,
    float* __restrict__ out)
{
    __shared__ float Hs[32 * 128];  // [k][r]
    __shared__ float Ws[32 * 64];   // [k][j]
    int t = threadIdx.x;
    int by = blockIdx.x;
    int row0 = by * 128;
    int tx = t & 15, ty = t >> 4;

    unsigned long long acc[8][2];
#pragma unroll
    for (int i = 0; i < 8; i++)
#pragma unroll
        for (int j = 0; j < 2; j++) acc[i][j] = 0ull;

    for (int kc = 0; kc < 256; kc += 32) {
        __syncthreads();
#pragma unroll
        for (int i = 0; i < 4; i++) {
            int u = t + i * 256;
            int r = u >> 3, kq = u & 7;
            int rg = row0 + r;
            float4 v = make_float4(0.f, 0.f, 0.f, 0.f);
            if (rg < NN) v = *(const float4*)(g_h + (size_t)rg * 256 + kc + kq * 4);
            Hs[(kq * 4 + 0) * 128 + r] = v.x;
            Hs[(kq * 4 + 1) * 128 + r] = v.y;
            Hs[(kq * 4 + 2) * 128 + r] = v.z;
            Hs[(kq * 4 + 3) * 128 + r] = v.w;
        }
#pragma unroll
        for (int i = 0; i < 2; i++) {
            int u = t + i * 256;
            int j = u >> 3, kq = u & 7;
            float4 v = *(const float4*)(Wp + (size_t)j * 256 + kc + kq * 4);
            Ws[(kq * 4 + 0) * 64 + j] = v.x;
            Ws[(kq * 4 + 1) * 64 + j] = v.y;
            Ws[(kq * 4 + 2) * 64 + j] = v.z;
            Ws[(kq * 4 + 3) * 64 + j] = v.w;
        }
        __syncthreads();
#pragma unroll
        for (int k = 0; k < 32; k++) {
            float a[8];
            *(float4*)(a)     = *(const float4*)&Hs[k * 128 + ty * 8];
            *(float4*)(a + 4) = *(const float4*)&Hs[k * 128 + ty * 8 + 4];
            float4 b4 = *(const float4*)&Ws[k * 64 + tx * 4];
            unsigned long long bpair[2];
            PACK2(bpair[0], b4.x, b4.y);
            PACK2(bpair[1], b4.z, b4.w);
#pragma unroll
            for (int i = 0; i < 8; i++) {
                unsigned long long ap;
                BCAST2(ap, a[i]);
                FMA2(acc[i][0], ap, bpair[0], acc[i][0]);
                FMA2(acc[i][1], ap, bpair[1], acc[i][1]);
            }
        }
    }
    float4 bias = *(const float4*)(bp + tx * 4);
#pragma unroll
    for (int i = 0; i < 8; i++) {
        int rg = row0 + ty * 8 + i;
        if (rg >= NN) continue;
        float4 xv = *(const float4*)(x + (size_t)rg * 64 + tx * 4);
        float c[4];
        UNPACK2(c[0], c[1], acc[i][0]);
        UNPACK2(c[2], c[3], acc[i][1]);
        float4 o;
        o.x = fmaxf(c[0] + bias.x + xv.x, 0.f);
        o.y = fmaxf(c[1] + bias.y + xv.y, 0.f);
        o.z = fmaxf(c[2] + bias.z + xv.z, 0.f);
        o.w = fmaxf(c[3] + bias.w + xv.w, 0.f);
        *(float4*)(out + (size_t)rg * 64 + tx * 4) = o;
    }
}

// ============================================================================
// Launch order note: CSR build first, GEMM 5th, so that attn_kernel is the
// 6th launch — the one the fixed ncu capture (-s 5 -c 1) profiles.
// ============================================================================
extern "C" void kernel_launch(void* const* d_in, const int* in_sizes, int n_in,
                              void* d_out, int out_size)
{
    const float* x     = (const float*)d_in[0];
    const int*   ei    = (const int*)d_in[1];
    const float* Wq    = (const float*)d_in[2];
    const float* bq    = (const float*)d_in[3];
    const float* Wk    = (const float*)d_in[4];
    const float* bk    = (const float*)d_in[5];
    const float* Wv    = (const float*)d_in[6];
    const float* bv    = (const float*)d_in[7];
    const float* Wsk   = (const float*)d_in[8];
    const float* bsk   = (const float*)d_in[9];
    const float* Wbeta = (const float*)d_in[10];
    const float* lng   = (const float*)d_in[11];
    const float* lnb   = (const float*)d_in[12];
    const float* Wp    = (const float*)d_in[13];
    const float* bp    = (const float*)d_in[14];
    float* out = (float*)d_out;

    void* dcp = nullptr;
    cudaGetSymbolAddress(&dcp, g_degcur);
    cudaMemsetAsync(dcp, 0, 2 * NN * sizeof(int));          // launch 1

    hist_kernel<<<2500, 256>>>(ei);                          // launch 2
    scan_kernel<<<1, 1024>>>();                              // launch 3
    scatter_kernel<<<2500, 256>>>(ei);                       // launch 4
    gemm_qkvs<<<dim3(8, 391), 256>>>(x, Wq, bq, Wk, bk, Wv, bv, Wsk, bsk); // launch 5
    attn_kernel<<<6250, 256>>>(Wbeta, lng, lnb);             // launch 6  <- profiled
    gemm_proj<<<391, 256>>>(x, Wp, bp, out);                 // launch 7
}

// round 7
// speedup vs baseline: 1.3102x; 1.3102x over previous
#include <cuda_runtime.h>
#include <cuda_bf16.h>
#include <cstdint>

#define NN 50000
#define EE 640000
#define QS 1024          // row stride of fused qkv/skip buffer

// ---- scratch (static device globals: allocation-free rule) ----
__device__ __align__(16) float g_buf[(size_t)NN * QS];   // [q|k|v|x_r] per node, 204.8MB
__device__ __align__(16) float g_h[(size_t)NN * 256];    // post-LN hidden, 51.2MB
__device__ int g_degcur[2 * NN];                          // [deg | cursor], one memset
__device__ int g_start[NN + 1];
__device__ int g_esrc[EE];

// ---- packed f32x2 helpers ----
#define PACK2(p, lo, hi)   asm("mov.b64 %0, {%1,%2};" : "=l"(p) : "f"(lo), "f"(hi))
#define BCAST2(p, v)       asm("mov.b64 %0, {%1,%1};" : "=l"(p) : "f"(v))
#define UNPACK2(lo, hi, p) asm("mov.b64 {%0,%1}, %2;" : "=f"(lo), "=f"(hi) : "l"(p))
#define FMA2(d, a, b, c)   asm("fma.rn.f32x2 %0, %1, %2, %3;" : "=l"(d) : "l"(a), "l"(b), "l"(c))

// ---- warp-level bf16 MMA (m16n8k16, fp32 accum) — compute_103-safe HMMA ----
__device__ __forceinline__ void mma16816(float* c, const uint32_t* a, const uint32_t* b) {
    asm volatile(
        "mma.sync.aligned.m16n8k16.row.col.f32.bf16.bf16.f32 "
        "{%0,%1,%2,%3}, {%4,%5,%6,%7}, {%8,%9}, {%0,%1,%2,%3};\n"
        : "+f"(c[0]), "+f"(c[1]), "+f"(c[2]), "+f"(c[3])
        : "r"(a[0]), "r"(a[1]), "r"(a[2]), "r"(a[3]), "r"(b[0]), "r"(b[1]));
}

#define AST 68   // smem row stride in bf16 (64 data + 4 pad; conflict-free LDS.32)
// smem layout (bf16 units): Ahi | Alo | Whi | Wlo | bias(float)
#define SMEM_QKV_BYTES (4 * 128 * AST * 2 + 512)

// ============================================================================
// Kernel 1 (HMMA): out[n, 1024] = x[n,64] @ [Wq|Wk|Wv|Wskip]^T + b
// 128x128 tile per block (8 warps, warp = 16 rows x 128 cols).
// bf16 hi/lo split, 3 accumulating term passes -> fp32-grade accuracy.
// ============================================================================
__global__ __launch_bounds__(256) void gemm_qkvs_mma(
    const float* __restrict__ x,
    const float* __restrict__ Wq, const float* __restrict__ bq,
    const float* __restrict__ Wk, const float* __restrict__ bk,
    const float* __restrict__ Wv, const float* __restrict__ bv,
    const float* __restrict__ Wsk, const float* __restrict__ bsk)
{
    extern __shared__ __nv_bfloat16 sm[];
    __nv_bfloat16* Ahi = sm;
    __nv_bfloat16* Alo = sm + 128 * AST;
    __nv_bfloat16* Whi = sm + 2 * 128 * AST;
    __nv_bfloat16* Wlo = sm + 3 * 128 * AST;
    float* sbias = (float*)(sm + 4 * 128 * AST);

    int t = threadIdx.x;
    int bx = blockIdx.x;             // col tile (0..7)
    int by = blockIdx.y;             // row tile (0..390)
    int c0 = bx * 128;
    int which = c0 >> 8;
    int dbase = c0 & 255;
    const float* W = (which == 0) ? Wq : (which == 1) ? Wk : (which == 2) ? Wv : Wsk;
    const float* B = (which == 0) ? bq : (which == 1) ? bk : (which == 2) ? bv : bsk;
    int row0 = by * 128;

    if (t < 128) sbias[t] = B[dbase + t];

    // ---- load + hi/lo split-convert: A = x tile [128,64], B = W tile [128,64]
    // 2048 (row,quad) units, 8 per thread.
#pragma unroll
    for (int i = 0; i < 8; i++) {
        int idx = t + i * 256;
        int r = idx >> 4, qd = idx & 15;
        int so = r * AST + qd * 4;
        // A = x
        float4 v = make_float4(0.f, 0.f, 0.f, 0.f);
        int rg = row0 + r;
        if (rg < NN) v = *(const float4*)(x + (size_t)rg * 64 + qd * 4);
        __nv_bfloat162 h0 = __floats2bfloat162_rn(v.x, v.y);
        __nv_bfloat162 h1 = __floats2bfloat162_rn(v.z, v.w);
        __nv_bfloat162 l0 = __floats2bfloat162_rn(v.x - __bfloat162float(__low2bfloat16(h0)),
                                                  v.y - __bfloat162float(__high2bfloat16(h0)));
        __nv_bfloat162 l1 = __floats2bfloat162_rn(v.z - __bfloat162float(__low2bfloat16(h1)),
                                                  v.w - __bfloat162float(__high2bfloat16(h1)));
        *(__nv_bfloat162*)(Ahi + so)     = h0;
        *(__nv_bfloat162*)(Ahi + so + 2) = h1;
        *(__nv_bfloat162*)(Alo + so)     = l0;
        *(__nv_bfloat162*)(Alo + so + 2) = l1;
        // B = W
        float4 w4 = *(const float4*)(W + (size_t)(dbase + r) * 64 + qd * 4);
        __nv_bfloat162 wh0 = __floats2bfloat162_rn(w4.x, w4.y);
        __nv_bfloat162 wh1 = __floats2bfloat162_rn(w4.z, w4.w);
        __nv_bfloat162 wl0 = __floats2bfloat162_rn(w4.x - __bfloat162float(__low2bfloat16(wh0)),
                                                   w4.y - __bfloat162float(__high2bfloat16(wh0)));
        __nv_bfloat162 wl1 = __floats2bfloat162_rn(w4.z - __bfloat162float(__low2bfloat16(wh1)),
                                                   w4.w - __bfloat162float(__high2bfloat16(wh1)));
        *(__nv_bfloat162*)(Whi + so)     = wh0;
        *(__nv_bfloat162*)(Whi + so + 2) = wh1;
        *(__nv_bfloat162*)(Wlo + so)     = wl0;
        *(__nv_bfloat162*)(Wlo + so + 2) = wl1;
    }
    __syncthreads();

    int wid = t >> 5, lane = t & 31;
    int g = lane >> 2, tq = lane & 3;
    int r0 = wid * 16;

    float acc[16][4];
#pragma unroll
    for (int nt = 0; nt < 16; nt++)
#pragma unroll
        for (int j = 0; j < 4; j++) acc[nt][j] = 0.f;

    const __nv_bfloat16* Asrc[3] = { Ahi, Ahi, Alo };
    const __nv_bfloat16* Bsrc[3] = { Whi, Wlo, Whi };
#pragma unroll
    for (int term = 0; term < 3; term++) {
        const __nv_bfloat16* Ap = Asrc[term];
        const __nv_bfloat16* Bp = Bsrc[term];
#pragma unroll
        for (int ks = 0; ks < 4; ks++) {
            int kb = ks * 16 + tq * 2;
            uint32_t a[4];
            a[0] = *(const uint32_t*)(Ap + (r0 + g) * AST + kb);
            a[1] = *(const uint32_t*)(Ap + (r0 + g + 8) * AST + kb);
            a[2] = *(const uint32_t*)(Ap + (r0 + g) * AST + kb + 8);
            a[3] = *(const uint32_t*)(Ap + (r0 + g + 8) * AST + kb + 8);
#pragma unroll
            for (int nt = 0; nt < 16; nt++) {
                int col = nt * 8 + g;
                uint32_t b[2];
                b[0] = *(const uint32_t*)(Bp + col * AST + kb);
                b[1] = *(const uint32_t*)(Bp + col * AST + kb + 8);
                mma16816(acc[nt], a, b);
            }
        }
    }

    // epilogue: bias + store. Thread holds rows (r0+g, r0+g+8), cols nt*8+tq*2,+1
    int rA = row0 + r0 + g;
    int rB = rA + 8;
#pragma unroll
    for (int nt = 0; nt < 16; nt++) {
        int lc = nt * 8 + tq * 2;
        float b0 = sbias[lc], b1 = sbias[lc + 1];
        if (rA < NN) {
            float2 o = make_float2(acc[nt][0] + b0, acc[nt][1] + b1);
            *(float2*)(g_buf + (size_t)rA * QS + c0 + lc) = o;
        }
        if (rB < NN) {
            float2 o = make_float2(acc[nt][2] + b0, acc[nt][3] + b1);
            *(float2*)(g_buf + (size_t)rB * QS + c0 + lc) = o;
        }
    }
}

// ============================================================================
// CSR build: histogram -> exclusive scan (single block) -> scatter
// ============================================================================
__global__ __launch_bounds__(256) void hist_kernel(const int* __restrict__ ei)
{
    int e = blockIdx.x * 256 + threadIdx.x;
    if (e < EE) atomicAdd(&g_degcur[ei[EE + e]], 1);
}

__global__ __launch_bounds__(1024) void scan_kernel()
{
    __shared__ int wsum[32];
    __shared__ int carryS;
    int t = threadIdx.x;
    int lane = t & 31, w = t >> 5;
    if (t == 0) carryS = 0;
    __syncthreads();
    for (int base = 0; base < NN; base += 1024) {
        int i = base + t;
        int v = (i < NN) ? g_degcur[i] : 0;
        int xv = v;
#pragma unroll
        for (int off = 1; off < 32; off <<= 1) {
            int u = __shfl_up_sync(0xffffffffu, xv, off);
            if (lane >= off) xv += u;
        }
        if (lane == 31) wsum[w] = xv;
        __syncthreads();
        if (w == 0) {
            int y = wsum[lane];
#pragma unroll
            for (int off = 1; off < 32; off <<= 1) {
                int u = __shfl_up_sync(0xffffffffu, y, off);
                if (lane >= off) y += u;
            }
            wsum[lane] = y;
        }
        __syncthreads();
        int incl = xv + (w ? wsum[w - 1] : 0);
        int c = carryS;
        if (i < NN) g_start[i] = c + incl - v;
        __syncthreads();
        if (t == 0) carryS = c + wsum[31];
        __syncthreads();
    }
    if (t == 0) g_start[NN] = carryS;
}

__global__ __launch_bounds__(256) void scatter_kernel(const int* __restrict__ ei)
{
    int e = blockIdx.x * 256 + threadIdx.x;
    if (e < EE) {
        int d = ei[EE + e];
        int s = ei[e];
        int pos = g_start[d] + atomicAdd(&g_degcur[NN + d], 1);
        g_esrc[pos] = s;
    }
}

// ============================================================================
// Kernel 3: warp-per-dst online-softmax attention + beta-gate + LN (R3 form).
// ============================================================================
__global__ __launch_bounds__(256) void attn_kernel(
    const float* __restrict__ Wbeta,
    const float* __restrict__ lng, const float* __restrict__ lnb)
{
    __shared__ float sWb[768];
    __shared__ float sg[256], sb[256];
    int t = threadIdx.x;
    for (int i = t; i < 768; i += 256) sWb[i] = Wbeta[i];
    if (t < 256) { sg[t] = lng[t]; sb[t] = lnb[t]; }
    __syncthreads();

    int warp = t >> 5, lane = t & 31;
    int node = blockIdx.x * 8 + warp;
    if (node >= NN) return;

    int c0 = lane * 8;
    const float* qp = g_buf + (size_t)node * QS + c0;
    float q[8];
    *(float4*)(q)     = *(const float4*)(qp);
    *(float4*)(q + 4) = *(const float4*)(qp + 4);
#pragma unroll
    for (int u = 0; u < 8; u++) q[u] *= 0.125f;   // 1/sqrt(64)

    float m = -1e30f, ssum = 0.f;
    float acc[8];
#pragma unroll
    for (int u = 0; u < 8; u++) acc[u] = 0.f;

    int e0 = g_start[node], e1 = g_start[node + 1];
    int src = (e0 < e1) ? g_esrc[e0] : 0;
    for (int e = e0; e < e1; e++) {
        const float* kp = g_buf + (size_t)src * QS + 256 + c0;
        float4 ka = *(const float4*)(kp);
        float4 kb = *(const float4*)(kp + 4);
        float4 va = *(const float4*)(kp + 256);
        float4 vb = *(const float4*)(kp + 260);
        int nsrc = (e + 1 < e1) ? g_esrc[e + 1] : 0;

        float p = q[0] * ka.x + q[1] * ka.y + q[2] * ka.z + q[3] * ka.w
                + q[4] * kb.x + q[5] * kb.y + q[6] * kb.z + q[7] * kb.w;
        p += __shfl_xor_sync(0xffffffffu, p, 1, 8);
        p += __shfl_xor_sync(0xffffffffu, p, 2, 8);
        p += __shfl_xor_sync(0xffffffffu, p, 4, 8);
        float mn = fmaxf(m, p);
        float sc = __expf(m - mn);
        float wgt = __expf(p - mn);
        m = mn;
        ssum = ssum * sc + wgt;
        acc[0] = acc[0] * sc + wgt * va.x;
        acc[1] = acc[1] * sc + wgt * va.y;
        acc[2] = acc[2] * sc + wgt * va.z;
        acc[3] = acc[3] * sc + wgt * va.w;
        acc[4] = acc[4] * sc + wgt * vb.x;
        acc[5] = acc[5] * sc + wgt * vb.y;
        acc[6] = acc[6] * sc + wgt * vb.z;
        acc[7] = acc[7] * sc + wgt * vb.w;
        src = nsrc;
    }
    float inv = 1.f / (ssum + 1e-16f);
    float outv[8];
#pragma unroll
    for (int u = 0; u < 8; u++) outv[u] = acc[u] * inv;

    const float* xp = g_buf + (size_t)node * QS + 768 + c0;
    float xr[8];
    *(float4*)(xr)     = *(const float4*)(xp);
    *(float4*)(xr + 4) = *(const float4*)(xp + 4);

    float part = 0.f;
#pragma unroll
    for (int u = 0; u < 8; u++) {
        int c = c0 + u;
        part += outv[u] * sWb[c] + xr[u] * sWb[256 + c] + (outv[u] - xr[u]) * sWb[512 + c];
    }
#pragma unroll
    for (int off = 16; off > 0; off >>= 1)
        part += __shfl_xor_sync(0xffffffffu, part, off);
    float beta = 1.f / (1.f + __expf(-part));

    float h[8], sum = 0.f, sq = 0.f;
#pragma unroll
    for (int u = 0; u < 8; u++) {
        h[u] = beta * xr[u] + (1.f - beta) * outv[u];
        sum += h[u];
        sq += h[u] * h[u];
    }
#pragma unroll
    for (int off = 16; off > 0; off >>= 1) {
        sum += __shfl_xor_sync(0xffffffffu, sum, off);
        sq  += __shfl_xor_sync(0xffffffffu, sq, off);
    }
    float mu = sum * (1.f / 256.f);
    float var = sq * (1.f / 256.f) - mu * mu;
    float rstd = rsqrtf(var + 1e-5f);

    float o[8];
#pragma unroll
    for (int u = 0; u < 8; u++) {
        int c = c0 + u;
        o[u] = (h[u] - mu) * rstd * sg[c] + sb[c];
    }
    float* hp = g_h + (size_t)node * 256 + c0;
    *(float4*)(hp)     = *(const float4*)(o);
    *(float4*)(hp + 4) = *(const float4*)(o + 4);
}

// ============================================================================
// Kernel 4: proj GEMM + bias + residual + ReLU (FFMA2 scalar).
// ============================================================================
__global__ __launch_bounds__(256) void gemm_proj(
    const float* __restrict__ x,
    const float* __restrict__ Wp, const float* __restrict__ bp,
    float* __restrict__ out)
{
    __shared__ float Hs[32 * 128];  // [k][r]
    __shared__ float Ws[32 * 64];   // [k][j]
    int t = threadIdx.x;
    int by = blockIdx.x;
    int row0 = by * 128;
    int tx = t & 15, ty = t >> 4;

    unsigned long long acc[8][2];
#pragma unroll
    for (int i = 0; i < 8; i++)
#pragma unroll
        for (int j = 0; j < 2; j++) acc[i][j] = 0ull;

    for (int kc = 0; kc < 256; kc += 32) {
        __syncthreads();
#pragma unroll
        for (int i = 0; i < 4; i++) {
            int u = t + i * 256;
            int r = u >> 3, kq = u & 7;
            int rg = row0 + r;
            float4 v = make_float4(0.f, 0.f, 0.f, 0.f);
            if (rg < NN) v = *(const float4*)(g_h + (size_t)rg * 256 + kc + kq * 4);
            Hs[(kq * 4 + 0) * 128 + r] = v.x;
            Hs[(kq * 4 + 1) * 128 + r] = v.y;
            Hs[(kq * 4 + 2) * 128 + r] = v.z;
            Hs[(kq * 4 + 3) * 128 + r] = v.w;
        }
#pragma unroll
        for (int i = 0; i < 2; i++) {
            int u = t + i * 256;
            int j = u >> 3, kq = u & 7;
            float4 v = *(const float4*)(Wp + (size_t)j * 256 + kc + kq * 4);
            Ws[(kq * 4 + 0) * 64 + j] = v.x;
            Ws[(kq * 4 + 1) * 64 + j] = v.y;
            Ws[(kq * 4 + 2) * 64 + j] = v.z;
            Ws[(kq * 4 + 3) * 64 + j] = v.w;
        }
        __syncthreads();
#pragma unroll
        for (int k = 0; k < 32; k++) {
            float a[8];
            *(float4*)(a)     = *(const float4*)&Hs[k * 128 + ty * 8];
            *(float4*)(a + 4) = *(const float4*)&Hs[k * 128 + ty * 8 + 4];
            float4 b4 = *(const float4*)&Ws[k * 64 + tx * 4];
            unsigned long long bpair[2];
            PACK2(bpair[0], b4.x, b4.y);
            PACK2(bpair[1], b4.z, b4.w);
#pragma unroll
            for (int i = 0; i < 8; i++) {
                unsigned long long ap;
                BCAST2(ap, a[i]);
                FMA2(acc[i][0], ap, bpair[0], acc[i][0]);
                FMA2(acc[i][1], ap, bpair[1], acc[i][1]);
            }
        }
    }
    float4 bias = *(const float4*)(bp + tx * 4);
#pragma unroll
    for (int i = 0; i < 8; i++) {
        int rg = row0 + ty * 8 + i;
        if (rg >= NN) continue;
        float4 xv = *(const float4*)(x + (size_t)rg * 64 + tx * 4);
        float c[4];
        UNPACK2(c[0], c[1], acc[i][0]);
        UNPACK2(c[2], c[3], acc[i][1]);
        float4 o;
        o.x = fmaxf(c[0] + bias.x + xv.x, 0.f);
        o.y = fmaxf(c[1] + bias.y + xv.y, 0.f);
        o.z = fmaxf(c[2] + bias.z + xv.z, 0.f);
        o.w = fmaxf(c[3] + bias.w + xv.w, 0.f);
        *(float4*)(out + (size_t)rg * 64 + tx * 4) = o;
    }
}

// ============================================================================
extern "C" void kernel_launch(void* const* d_in, const int* in_sizes, int n_in,
                              void* d_out, int out_size)
{
    const float* x     = (const float*)d_in[0];
    const int*   ei    = (const int*)d_in[1];
    const float* Wq    = (const float*)d_in[2];
    const float* bq    = (const float*)d_in[3];
    const float* Wk    = (const float*)d_in[4];
    const float* bk    = (const float*)d_in[5];
    const float* Wv    = (const float*)d_in[6];
    const float* bv    = (const float*)d_in[7];
    const float* Wsk   = (const float*)d_in[8];
    const float* bsk   = (const float*)d_in[9];
    const float* Wbeta = (const float*)d_in[10];
    const float* lng   = (const float*)d_in[11];
    const float* lnb   = (const float*)d_in[12];
    const float* Wp    = (const float*)d_in[13];
    const float* bp    = (const float*)d_in[14];
    float* out = (float*)d_out;

    static int attr_set = 0;
    if (!attr_set) {
        cudaFuncSetAttribute(gemm_qkvs_mma,
                             cudaFuncAttributeMaxDynamicSharedMemorySize,
                             SMEM_QKV_BYTES);
        attr_set = 1;
    }

    void* dcp = nullptr;
    cudaGetSymbolAddress(&dcp, g_degcur);
    cudaMemsetAsync(dcp, 0, 2 * NN * sizeof(int));

    hist_kernel<<<2500, 256>>>(ei);
    scan_kernel<<<1, 1024>>>();
    scatter_kernel<<<2500, 256>>>(ei);
    gemm_qkvs_mma<<<dim3(8, 391), 256, SMEM_QKV_BYTES>>>(x, Wq, bq, Wk, bk, Wv, bv, Wsk, bsk);
    attn_kernel<<<6250, 256>>>(Wbeta, lng, lnb);
    gemm_proj<<<391, 256>>>(x, Wp, bp, out);
}

// round 8
// speedup vs baseline: 1.3152x; 1.0038x over previous
#include <cuda_runtime.h>
#include <cuda_bf16.h>
#include <cstdint>

#define NN 50000
#define EE 640000
#define QS 1024          // row stride of fused qkv/skip buffer

// ---- scratch (static device globals: allocation-free rule) ----
__device__ __align__(16) float g_buf[(size_t)NN * QS];   // [q|k|v|x_r] per node, 204.8MB
__device__ __align__(16) float g_h[(size_t)NN * 256];    // post-LN hidden, 51.2MB
__device__ int g_degcur[2 * NN];                          // [deg | cursor], one memset
__device__ int g_start[NN + 1];
__device__ int g_esrc[EE];

// ---- packed f32x2 helpers ----
#define PACK2(p, lo, hi)   asm("mov.b64 %0, {%1,%2};" : "=l"(p) : "f"(lo), "f"(hi))
#define BCAST2(p, v)       asm("mov.b64 %0, {%1,%1};" : "=l"(p) : "f"(v))
#define UNPACK2(lo, hi, p) asm("mov.b64 {%0,%1}, %2;" : "=f"(lo), "=f"(hi) : "l"(p))
#define FMA2(d, a, b, c)   asm("fma.rn.f32x2 %0, %1, %2, %3;" : "=l"(d) : "l"(a), "l"(b), "l"(c))

// ---- warp-level bf16 MMA (m16n8k16, fp32 accum) — compute_103-safe HMMA ----
__device__ __forceinline__ void mma16816(float* c, const uint32_t* a, const uint32_t* b) {
    asm volatile(
        "mma.sync.aligned.m16n8k16.row.col.f32.bf16.bf16.f32 "
        "{%0,%1,%2,%3}, {%4,%5,%6,%7}, {%8,%9}, {%0,%1,%2,%3};\n"
        : "+f"(c[0]), "+f"(c[1]), "+f"(c[2]), "+f"(c[3])
        : "r"(a[0]), "r"(a[1]), "r"(a[2]), "r"(a[3]), "r"(b[0]), "r"(b[1]));
}

#define AST 68   // smem row stride in bf16 (64 data + 4 pad; conflict-free LDS.32)
// smem layout (bf16 units): Ahi | Alo | Whi | Wlo | bias(float)
#define SMEM_QKV_BYTES (4 * 128 * AST * 2 + 512)

// ============================================================================
// Kernel 1 (HMMA): out[n, 1024] = x[n,64] @ [Wq|Wk|Wv|Wskip]^T + b
// 128x128 tile per block (8 warps, warp = 16 rows x 128 cols).
// bf16 hi/lo split, 3 accumulating term passes -> fp32-grade accuracy.
// ============================================================================
__global__ __launch_bounds__(256) void gemm_qkvs_mma(
    const float* __restrict__ x,
    const float* __restrict__ Wq, const float* __restrict__ bq,
    const float* __restrict__ Wk, const float* __restrict__ bk,
    const float* __restrict__ Wv, const float* __restrict__ bv,
    const float* __restrict__ Wsk, const float* __restrict__ bsk)
{
    extern __shared__ __nv_bfloat16 sm[];
    __nv_bfloat16* Ahi = sm;
    __nv_bfloat16* Alo = sm + 128 * AST;
    __nv_bfloat16* Whi = sm + 2 * 128 * AST;
    __nv_bfloat16* Wlo = sm + 3 * 128 * AST;
    float* sbias = (float*)(sm + 4 * 128 * AST);

    int t = threadIdx.x;
    int bx = blockIdx.x;             // col tile (0..7)
    int by = blockIdx.y;             // row tile (0..390)
    int c0 = bx * 128;
    int which = c0 >> 8;
    int dbase = c0 & 255;
    const float* W = (which == 0) ? Wq : (which == 1) ? Wk : (which == 2) ? Wv : Wsk;
    const float* B = (which == 0) ? bq : (which == 1) ? bk : (which == 2) ? bv : bsk;
    int row0 = by * 128;

    if (t < 128) sbias[t] = B[dbase + t];

    // ---- load + hi/lo split-convert: A = x tile [128,64], B = W tile [128,64]
    // 2048 (row,quad) units, 8 per thread.
#pragma unroll
    for (int i = 0; i < 8; i++) {
        int idx = t + i * 256;
        int r = idx >> 4, qd = idx & 15;
        int so = r * AST + qd * 4;
        // A = x
        float4 v = make_float4(0.f, 0.f, 0.f, 0.f);
        int rg = row0 + r;
        if (rg < NN) v = *(const float4*)(x + (size_t)rg * 64 + qd * 4);
        __nv_bfloat162 h0 = __floats2bfloat162_rn(v.x, v.y);
        __nv_bfloat162 h1 = __floats2bfloat162_rn(v.z, v.w);
        __nv_bfloat162 l0 = __floats2bfloat162_rn(v.x - __bfloat162float(__low2bfloat16(h0)),
                                                  v.y - __bfloat162float(__high2bfloat16(h0)));
        __nv_bfloat162 l1 = __floats2bfloat162_rn(v.z - __bfloat162float(__low2bfloat16(h1)),
                                                  v.w - __bfloat162float(__high2bfloat16(h1)));
        *(__nv_bfloat162*)(Ahi + so)     = h0;
        *(__nv_bfloat162*)(Ahi + so + 2) = h1;
        *(__nv_bfloat162*)(Alo + so)     = l0;
        *(__nv_bfloat162*)(Alo + so + 2) = l1;
        // B = W
        float4 w4 = *(const float4*)(W + (size_t)(dbase + r) * 64 + qd * 4);
        __nv_bfloat162 wh0 = __floats2bfloat162_rn(w4.x, w4.y);
        __nv_bfloat162 wh1 = __floats2bfloat162_rn(w4.z, w4.w);
        __nv_bfloat162 wl0 = __floats2bfloat162_rn(w4.x - __bfloat162float(__low2bfloat16(wh0)),
                                                   w4.y - __bfloat162float(__high2bfloat16(wh0)));
        __nv_bfloat162 wl1 = __floats2bfloat162_rn(w4.z - __bfloat162float(__low2bfloat16(wh1)),
                                                   w4.w - __bfloat162float(__high2bfloat16(wh1)));
        *(__nv_bfloat162*)(Whi + so)     = wh0;
        *(__nv_bfloat162*)(Whi + so + 2) = wh1;
        *(__nv_bfloat162*)(Wlo + so)     = wl0;
        *(__nv_bfloat162*)(Wlo + so + 2) = wl1;
    }
    __syncthreads();

    int wid = t >> 5, lane = t & 31;
    int g = lane >> 2, tq = lane & 3;
    int r0 = wid * 16;

    float acc[16][4];
#pragma unroll
    for (int nt = 0; nt < 16; nt++)
#pragma unroll
        for (int j = 0; j < 4; j++) acc[nt][j] = 0.f;

    const __nv_bfloat16* Asrc[3] = { Ahi, Ahi, Alo };
    const __nv_bfloat16* Bsrc[3] = { Whi, Wlo, Whi };
#pragma unroll
    for (int term = 0; term < 3; term++) {
        const __nv_bfloat16* Ap = Asrc[term];
        const __nv_bfloat16* Bp = Bsrc[term];
#pragma unroll
        for (int ks = 0; ks < 4; ks++) {
            int kb = ks * 16 + tq * 2;
            uint32_t a[4];
            a[0] = *(const uint32_t*)(Ap + (r0 + g) * AST + kb);
            a[1] = *(const uint32_t*)(Ap + (r0 + g + 8) * AST + kb);
            a[2] = *(const uint32_t*)(Ap + (r0 + g) * AST + kb + 8);
            a[3] = *(const uint32_t*)(Ap + (r0 + g + 8) * AST + kb + 8);
#pragma unroll
            for (int nt = 0; nt < 16; nt++) {
                int col = nt * 8 + g;
                uint32_t b[2];
                b[0] = *(const uint32_t*)(Bp + col * AST + kb);
                b[1] = *(const uint32_t*)(Bp + col * AST + kb + 8);
                mma16816(acc[nt], a, b);
            }
        }
    }

    // epilogue: bias + store. Thread holds rows (r0+g, r0+g+8), cols nt*8+tq*2,+1
    int rA = row0 + r0 + g;
    int rB = rA + 8;
#pragma unroll
    for (int nt = 0; nt < 16; nt++) {
        int lc = nt * 8 + tq * 2;
        float b0 = sbias[lc], b1 = sbias[lc + 1];
        if (rA < NN) {
            float2 o = make_float2(acc[nt][0] + b0, acc[nt][1] + b1);
            *(float2*)(g_buf + (size_t)rA * QS + c0 + lc) = o;
        }
        if (rB < NN) {
            float2 o = make_float2(acc[nt][2] + b0, acc[nt][3] + b1);
            *(float2*)(g_buf + (size_t)rB * QS + c0 + lc) = o;
        }
    }
}

// ============================================================================
// CSR build: histogram -> exclusive scan (single block) -> scatter
// ============================================================================
__global__ __launch_bounds__(256) void hist_kernel(const int* __restrict__ ei)
{
    int e = blockIdx.x * 256 + threadIdx.x;
    if (e < EE) atomicAdd(&g_degcur[ei[EE + e]], 1);
}

__global__ __launch_bounds__(1024) void scan_kernel()
{
    __shared__ int wsum[32];
    __shared__ int carryS;
    int t = threadIdx.x;
    int lane = t & 31, w = t >> 5;
    if (t == 0) carryS = 0;
    __syncthreads();
    for (int base = 0; base < NN; base += 1024) {
        int i = base + t;
        int v = (i < NN) ? g_degcur[i] : 0;
        int xv = v;
#pragma unroll
        for (int off = 1; off < 32; off <<= 1) {
            int u = __shfl_up_sync(0xffffffffu, xv, off);
            if (lane >= off) xv += u;
        }
        if (lane == 31) wsum[w] = xv;
        __syncthreads();
        if (w == 0) {
            int y = wsum[lane];
#pragma unroll
            for (int off = 1; off < 32; off <<= 1) {
                int u = __shfl_up_sync(0xffffffffu, y, off);
                if (lane >= off) y += u;
            }
            wsum[lane] = y;
        }
        __syncthreads();
        int incl = xv + (w ? wsum[w - 1] : 0);
        int c = carryS;
        if (i < NN) g_start[i] = c + incl - v;
        __syncthreads();
        if (t == 0) carryS = c + wsum[31];
        __syncthreads();
    }
    if (t == 0) g_start[NN] = carryS;
}

__global__ __launch_bounds__(256) void scatter_kernel(const int* __restrict__ ei)
{
    int e = blockIdx.x * 256 + threadIdx.x;
    if (e < EE) {
        int d = ei[EE + e];
        int s = ei[e];
        int pos = g_start[d] + atomicAdd(&g_degcur[NN + d], 1);
        g_esrc[pos] = s;
    }
}

// ============================================================================
// Kernel 3: warp-per-dst online-softmax attention + beta-gate + LN (R3 form).
// ============================================================================
__global__ __launch_bounds__(256) void attn_kernel(
    const float* __restrict__ Wbeta,
    const float* __restrict__ lng, const float* __restrict__ lnb)
{
    __shared__ float sWb[768];
    __shared__ float sg[256], sb[256];
    int t = threadIdx.x;
    for (int i = t; i < 768; i += 256) sWb[i] = Wbeta[i];
    if (t < 256) { sg[t] = lng[t]; sb[t] = lnb[t]; }
    __syncthreads();

    int warp = t >> 5, lane = t & 31;
    int node = blockIdx.x * 8 + warp;
    if (node >= NN) return;

    int c0 = lane * 8;
    const float* qp = g_buf + (size_t)node * QS + c0;
    float q[8];
    *(float4*)(q)     = *(const float4*)(qp);
    *(float4*)(q + 4) = *(const float4*)(qp + 4);
#pragma unroll
    for (int u = 0; u < 8; u++) q[u] *= 0.125f;   // 1/sqrt(64)

    float m = -1e30f, ssum = 0.f;
    float acc[8];
#pragma unroll
    for (int u = 0; u < 8; u++) acc[u] = 0.f;

    int e0 = g_start[node], e1 = g_start[node + 1];
    int src = (e0 < e1) ? g_esrc[e0] : 0;
    for (int e = e0; e < e1; e++) {
        const float* kp = g_buf + (size_t)src * QS + 256 + c0;
        float4 ka = *(const float4*)(kp);
        float4 kb = *(const float4*)(kp + 4);
        float4 va = *(const float4*)(kp + 256);
        float4 vb = *(const float4*)(kp + 260);
        int nsrc = (e + 1 < e1) ? g_esrc[e + 1] : 0;

        float p = q[0] * ka.x + q[1] * ka.y + q[2] * ka.z + q[3] * ka.w
                + q[4] * kb.x + q[5] * kb.y + q[6] * kb.z + q[7] * kb.w;
        p += __shfl_xor_sync(0xffffffffu, p, 1, 8);
        p += __shfl_xor_sync(0xffffffffu, p, 2, 8);
        p += __shfl_xor_sync(0xffffffffu, p, 4, 8);
        float mn = fmaxf(m, p);
        float sc = __expf(m - mn);
        float wgt = __expf(p - mn);
        m = mn;
        ssum = ssum * sc + wgt;
        acc[0] = acc[0] * sc + wgt * va.x;
        acc[1] = acc[1] * sc + wgt * va.y;
        acc[2] = acc[2] * sc + wgt * va.z;
        acc[3] = acc[3] * sc + wgt * va.w;
        acc[4] = acc[4] * sc + wgt * vb.x;
        acc[5] = acc[5] * sc + wgt * vb.y;
        acc[6] = acc[6] * sc + wgt * vb.z;
        acc[7] = acc[7] * sc + wgt * vb.w;
        src = nsrc;
    }
    float inv = 1.f / (ssum + 1e-16f);
    float outv[8];
#pragma unroll
    for (int u = 0; u < 8; u++) outv[u] = acc[u] * inv;

    const float* xp = g_buf + (size_t)node * QS + 768 + c0;
    float xr[8];
    *(float4*)(xr)     = *(const float4*)(xp);
    *(float4*)(xr + 4) = *(const float4*)(xp + 4);

    float part = 0.f;
#pragma unroll
    for (int u = 0; u < 8; u++) {
        int c = c0 + u;
        part += outv[u] * sWb[c] + xr[u] * sWb[256 + c] + (outv[u] - xr[u]) * sWb[512 + c];
    }
#pragma unroll
    for (int off = 16; off > 0; off >>= 1)
        part += __shfl_xor_sync(0xffffffffu, part, off);
    float beta = 1.f / (1.f + __expf(-part));

    float h[8], sum = 0.f, sq = 0.f;
#pragma unroll
    for (int u = 0; u < 8; u++) {
        h[u] = beta * xr[u] + (1.f - beta) * outv[u];
        sum += h[u];
        sq += h[u] * h[u];
    }
#pragma unroll
    for (int off = 16; off > 0; off >>= 1) {
        sum += __shfl_xor_sync(0xffffffffu, sum, off);
        sq  += __shfl_xor_sync(0xffffffffu, sq, off);
    }
    float mu = sum * (1.f / 256.f);
    float var = sq * (1.f / 256.f) - mu * mu;
    float rstd = rsqrtf(var + 1e-5f);

    float o[8];
#pragma unroll
    for (int u = 0; u < 8; u++) {
        int c = c0 + u;
        o[u] = (h[u] - mu) * rstd * sg[c] + sb[c];
    }
    float* hp = g_h + (size_t)node * 256 + c0;
    *(float4*)(hp)     = *(const float4*)(o);
    *(float4*)(hp + 4) = *(const float4*)(o + 4);
}

// ============================================================================
// Kernel 4: proj GEMM + bias + residual + ReLU (FFMA2 scalar).
// ============================================================================
__global__ __launch_bounds__(256) void gemm_proj(
    const float* __restrict__ x,
    const float* __restrict__ Wp, const float* __restrict__ bp,
    float* __restrict__ out)
{
    __shared__ float Hs[32 * 128];  // [k][r]
    __shared__ float Ws[32 * 64];   // [k][j]
    int t = threadIdx.x;
    int by = blockIdx.x;
    int row0 = by * 128;
    int tx = t & 15, ty = t >> 4;

    unsigned long long acc[8][2];
#pragma unroll
    for (int i = 0; i < 8; i++)
#pragma unroll
        for (int j = 0; j < 2; j++) acc[i][j] = 0ull;

    for (int kc = 0; kc < 256; kc += 32) {
        __syncthreads();
#pragma unroll
        for (int i = 0; i < 4; i++) {
            int u = t + i * 256;
            int r = u >> 3, kq = u & 7;
            int rg = row0 + r;
            float4 v = make_float4(0.f, 0.f, 0.f, 0.f);
            if (rg < NN) v = *(const float4*)(g_h + (size_t)rg * 256 + kc + kq * 4);
            Hs[(kq * 4 + 0) * 128 + r] = v.x;
            Hs[(kq * 4 + 1) * 128 + r] = v.y;
            Hs[(kq * 4 + 2) * 128 + r] = v.z;
            Hs[(kq * 4 + 3) * 128 + r] = v.w;
        }
#pragma unroll
        for (int i = 0; i < 2; i++) {
            int u = t + i * 256;
            int j = u >> 3, kq = u & 7;
            float4 v = *(const float4*)(Wp + (size_t)j * 256 + kc + kq * 4);
            Ws[(kq * 4 + 0) * 64 + j] = v.x;
            Ws[(kq * 4 + 1) * 64 + j] = v.y;
            Ws[(kq * 4 + 2) * 64 + j] = v.z;
            Ws[(kq * 4 + 3) * 64 + j] = v.w;
        }
        __syncthreads();
#pragma unroll
        for (int k = 0; k < 32; k++) {
            float a[8];
            *(float4*)(a)     = *(const float4*)&Hs[k * 128 + ty * 8];
            *(float4*)(a + 4) = *(const float4*)&Hs[k * 128 + ty * 8 + 4];
            float4 b4 = *(const float4*)&Ws[k * 64 + tx * 4];
            unsigned long long bpair[2];
            PACK2(bpair[0], b4.x, b4.y);
            PACK2(bpair[1], b4.z, b4.w);
#pragma unroll
            for (int i = 0; i < 8; i++) {
                unsigned long long ap;
                BCAST2(ap, a[i]);
                FMA2(acc[i][0], ap, bpair[0], acc[i][0]);
                FMA2(acc[i][1], ap, bpair[1], acc[i][1]);
            }
        }
    }
    float4 bias = *(const float4*)(bp + tx * 4);
#pragma unroll
    for (int i = 0; i < 8; i++) {
        int rg = row0 + ty * 8 + i;
        if (rg >= NN) continue;
        float4 xv = *(const float4*)(x + (size_t)rg * 64 + tx * 4);
        float c[4];
        UNPACK2(c[0], c[1], acc[i][0]);
        UNPACK2(c[2], c[3], acc[i][1]);
        float4 o;
        o.x = fmaxf(c[0] + bias.x + xv.x, 0.f);
        o.y = fmaxf(c[1] + bias.y + xv.y, 0.f);
        o.z = fmaxf(c[2] + bias.z + xv.z, 0.f);
        o.w = fmaxf(c[3] + bias.w + xv.w, 0.f);
        *(float4*)(out + (size_t)rg * 64 + tx * 4) = o;
    }
}

// ============================================================================
extern "C" void kernel_launch(void* const* d_in, const int* in_sizes, int n_in,
                              void* d_out, int out_size)
{
    const float* x     = (const float*)d_in[0];
    const int*   ei    = (const int*)d_in[1];
    const float* Wq    = (const float*)d_in[2];
    const float* bq    = (const float*)d_in[3];
    const float* Wk    = (const float*)d_in[4];
    const float* bk    = (const float*)d_in[5];
    const float* Wv    = (const float*)d_in[6];
    const float* bv    = (const float*)d_in[7];
    const float* Wsk   = (const float*)d_in[8];
    const float* bsk   = (const float*)d_in[9];
    const float* Wbeta = (const float*)d_in[10];
    const float* lng   = (const float*)d_in[11];
    const float* lnb   = (const float*)d_in[12];
    const float* Wp    = (const float*)d_in[13];
    const float* bp    = (const float*)d_in[14];
    float* out = (float*)d_out;

    static int attr_set = 0;
    if (!attr_set) {
        cudaFuncSetAttribute(gemm_qkvs_mma,
                             cudaFuncAttributeMaxDynamicSharedMemorySize,
                             SMEM_QKV_BYTES);
        attr_set = 1;
    }

    void* dcp = nullptr;
    cudaGetSymbolAddress(&dcp, g_degcur);
    cudaMemsetAsync(dcp, 0, 2 * NN * sizeof(int));

    hist_kernel<<<2500, 256>>>(ei);
    scan_kernel<<<1, 1024>>>();
    scatter_kernel<<<2500, 256>>>(ei);
    gemm_qkvs_mma<<<dim3(8, 391), 256, SMEM_QKV_BYTES>>>(x, Wq, bq, Wk, bk, Wv, bv, Wsk, bsk);
    attn_kernel<<<6250, 256>>>(Wbeta, lng, lnb);
    gemm_proj<<<391, 256>>>(x, Wp, bp, out);
}

// round 9
// speedup vs baseline: 1.4503x; 1.1028x over previous
#include <cuda_runtime.h>
#include <cuda_bf16.h>
#include <cstdint>

#define NN 50000
#define EE 640000
#define QS 1024          // row stride of fused qkv/skip buffer

// ---- scratch (static device globals: allocation-free rule) ----
__device__ __align__(16) float g_buf[(size_t)NN * QS];            // [q|k|v|x_r], 204.8MB
__device__ __align__(16) __nv_bfloat16 g_hhi[(size_t)NN * 256];   // h hi plane, 25.6MB
__device__ __align__(16) __nv_bfloat16 g_hlo[(size_t)NN * 256];   // h lo plane, 25.6MB
__device__ int g_degcur[2 * NN];
__device__ int g_start[NN + 1];
__device__ int g_esrc[EE];

// ---- warp-level bf16 MMA (m16n8k16, fp32 accum) ----
__device__ __forceinline__ void mma16816(float* c, const uint32_t* a, const uint32_t* b) {
    asm volatile(
        "mma.sync.aligned.m16n8k16.row.col.f32.bf16.bf16.f32 "
        "{%0,%1,%2,%3}, {%4,%5,%6,%7}, {%8,%9}, {%0,%1,%2,%3};\n"
        : "+f"(c[0]), "+f"(c[1]), "+f"(c[2]), "+f"(c[3])
        : "r"(a[0]), "r"(a[1]), "r"(a[2]), "r"(a[3]), "r"(b[0]), "r"(b[1]));
}
#define LDMX4(r, addr)                                                            \
    asm volatile("ldmatrix.sync.aligned.m8n8.x4.shared.b16 {%0,%1,%2,%3}, [%4];"  \
        : "=r"((r)[0]), "=r"((r)[1]), "=r"((r)[2]), "=r"((r)[3]) : "r"(addr))

__device__ __forceinline__ uint32_t smem_u32(const void* p) {
    uint32_t a;
    asm("{ .reg .u64 t; cvta.to.shared.u64 t, %1; cvt.u32.u64 %0, t; }" : "=r"(a) : "l"(p));
    return a;
}
// split float -> (hi, lo) bf16 pair packed as bf162
__device__ __forceinline__ void split2(float x0, float x1, __nv_bfloat162& hi, __nv_bfloat162& lo) {
    hi = __floats2bfloat162_rn(x0, x1);
    lo = __floats2bfloat162_rn(x0 - __bfloat162float(__low2bfloat16(hi)),
                               x1 - __bfloat162float(__high2bfloat16(hi)));
}

#define AST 72   // smem row stride in bf16 (conflict-free for ldmatrix: 144B = 36 banks)

// gemm_qkvs smem: Ahi|Alo|Whi|Wlo each 128*AST bf16, + 128 floats bias
#define QKV_SMEM_BYTES (4 * 128 * AST * 2 + 512)
// proj smem: Hhi|Hlo 128*AST + Whi|Wlo 64*AST (bf16) + 64 floats bias
#define PROJ_SMEM_BYTES ((2 * 128 * AST + 2 * 64 * AST) * 2 + 256)

// ============================================================================
// Kernel 1 (HMMA + ldmatrix): g_buf[n,1024] = x[n,64] @ [Wq|Wk|Wv|Wskip]^T + b
// 128x128 tile/block, 8 warps (warp = 16 rows x 128 cols).
// bf16 hi/lo split, 3 accumulating terms (hi*hi + hi*lo + lo*hi).
// ============================================================================
__global__ __launch_bounds__(256) void gemm_qkvs_mma(
    const float* __restrict__ x,
    const float* __restrict__ Wq, const float* __restrict__ bq,
    const float* __restrict__ Wk, const float* __restrict__ bk,
    const float* __restrict__ Wv, const float* __restrict__ bv,
    const float* __restrict__ Wsk, const float* __restrict__ bsk)
{
    extern __shared__ __nv_bfloat16 sm[];
    __nv_bfloat16* Ahi = sm;
    __nv_bfloat16* Alo = sm + 128 * AST;
    __nv_bfloat16* Whi = sm + 2 * 128 * AST;
    __nv_bfloat16* Wlo = sm + 3 * 128 * AST;
    float* sbias = (float*)(sm + 4 * 128 * AST);

    int t = threadIdx.x;
    int bx = blockIdx.x, by = blockIdx.y;
    int c0 = bx * 128;
    int which = c0 >> 8, dbase = c0 & 255;
    const float* W = (which == 0) ? Wq : (which == 1) ? Wk : (which == 2) ? Wv : Wsk;
    const float* B = (which == 0) ? bq : (which == 1) ? bk : (which == 2) ? bv : bsk;
    int row0 = by * 128;

    if (t < 128) sbias[t] = B[dbase + t];

    // load + hi/lo split-convert: A = x tile [128,64], B = W tile [128,64]
#pragma unroll
    for (int i = 0; i < 8; i++) {
        int idx = t + i * 256;
        int r = idx >> 4, qd = idx & 15;
        int so = r * AST + qd * 4;
        float4 v = make_float4(0.f, 0.f, 0.f, 0.f);
        int rg = row0 + r;
        if (rg < NN) v = *(const float4*)(x + (size_t)rg * 64 + qd * 4);
        __nv_bfloat162 h0, l0, h1, l1;
        split2(v.x, v.y, h0, l0);
        split2(v.z, v.w, h1, l1);
        *(__nv_bfloat162*)(Ahi + so) = h0;  *(__nv_bfloat162*)(Ahi + so + 2) = h1;
        *(__nv_bfloat162*)(Alo + so) = l0;  *(__nv_bfloat162*)(Alo + so + 2) = l1;
        float4 w4 = *(const float4*)(W + (size_t)(dbase + r) * 64 + qd * 4);
        split2(w4.x, w4.y, h0, l0);
        split2(w4.z, w4.w, h1, l1);
        *(__nv_bfloat162*)(Whi + so) = h0;  *(__nv_bfloat162*)(Whi + so + 2) = h1;
        *(__nv_bfloat162*)(Wlo + so) = l0;  *(__nv_bfloat162*)(Wlo + so + 2) = l1;
    }
    __syncthreads();

    int wid = t >> 5, lane = t & 31;
    int g = lane >> 2, tq = lane & 3;
    int r0 = wid * 16;

    // ldmatrix lane-address offsets (bf16 elements)
    int aoff = (r0 + (lane & 15)) * AST + (lane >> 4) * 8;
    uint32_t aHiB = smem_u32(Ahi) + aoff * 2;
    uint32_t aLoB = smem_u32(Alo) + aoff * 2;
    int bcol = ((lane >> 4) << 3) + (lane & 7);
    int bkh = ((lane >> 3) & 1) * 8;
    uint32_t bHiB = smem_u32(Whi) + (bcol * AST + bkh) * 2;
    uint32_t bLoB = smem_u32(Wlo) + (bcol * AST + bkh) * 2;

    float acc[16][4];
#pragma unroll
    for (int nt = 0; nt < 16; nt++)
#pragma unroll
        for (int j = 0; j < 4; j++) acc[nt][j] = 0.f;

#pragma unroll
    for (int ks = 0; ks < 4; ks++) {
        uint32_t kbB = ks * 32;  // 16 bf16 = 32 bytes
        uint32_t ahi[4], alo[4];
        LDMX4(ahi, aHiB + kbB);
        LDMX4(alo, aLoB + kbB);
#pragma unroll
        for (int ntg = 0; ntg < 8; ntg++) {
            uint32_t cgB = (uint32_t)(ntg * 16 * AST * 2);
            uint32_t bh[4], bl[4];
            LDMX4(bh, bHiB + cgB + kbB);
            LDMX4(bl, bLoB + cgB + kbB);
            mma16816(acc[2 * ntg],     ahi, bh);
            mma16816(acc[2 * ntg + 1], ahi, bh + 2);
            mma16816(acc[2 * ntg],     ahi, bl);
            mma16816(acc[2 * ntg + 1], ahi, bl + 2);
            mma16816(acc[2 * ntg],     alo, bh);
            mma16816(acc[2 * ntg + 1], alo, bh + 2);
        }
    }

    int rA = row0 + r0 + g;
    int rB = rA + 8;
#pragma unroll
    for (int nt = 0; nt < 16; nt++) {
        int lc = nt * 8 + tq * 2;
        float b0 = sbias[lc], b1 = sbias[lc + 1];
        if (rA < NN)
            *(float2*)(g_buf + (size_t)rA * QS + c0 + lc) = make_float2(acc[nt][0] + b0, acc[nt][1] + b1);
        if (rB < NN)
            *(float2*)(g_buf + (size_t)rB * QS + c0 + lc) = make_float2(acc[nt][2] + b0, acc[nt][3] + b1);
    }
}

// ============================================================================
// CSR build: histogram -> exclusive scan (single block) -> scatter
// ============================================================================
__global__ __launch_bounds__(256) void hist_kernel(const int* __restrict__ ei)
{
    int e = blockIdx.x * 256 + threadIdx.x;
    if (e < EE) atomicAdd(&g_degcur[ei[EE + e]], 1);
}

__global__ __launch_bounds__(1024) void scan_kernel()
{
    __shared__ int wsum[32];
    __shared__ int carryS;
    int t = threadIdx.x;
    int lane = t & 31, w = t >> 5;
    if (t == 0) carryS = 0;
    __syncthreads();
    for (int base = 0; base < NN; base += 1024) {
        int i = base + t;
        int v = (i < NN) ? g_degcur[i] : 0;
        int xv = v;
#pragma unroll
        for (int off = 1; off < 32; off <<= 1) {
            int u = __shfl_up_sync(0xffffffffu, xv, off);
            if (lane >= off) xv += u;
        }
        if (lane == 31) wsum[w] = xv;
        __syncthreads();
        if (w == 0) {
            int y = wsum[lane];
#pragma unroll
            for (int off = 1; off < 32; off <<= 1) {
                int u = __shfl_up_sync(0xffffffffu, y, off);
                if (lane >= off) y += u;
            }
            wsum[lane] = y;
        }
        __syncthreads();
        int incl = xv + (w ? wsum[w - 1] : 0);
        int c = carryS;
        if (i < NN) g_start[i] = c + incl - v;
        __syncthreads();
        if (t == 0) carryS = c + wsum[31];
        __syncthreads();
    }
    if (t == 0) g_start[NN] = carryS;
}

__global__ __launch_bounds__(256) void scatter_kernel(const int* __restrict__ ei)
{
    int e = blockIdx.x * 256 + threadIdx.x;
    if (e < EE) {
        int d = ei[EE + e];
        int s = ei[e];
        int pos = g_start[d] + atomicAdd(&g_degcur[NN + d], 1);
        g_esrc[pos] = s;
    }
}

// ============================================================================
// Kernel 3: warp-per-dst online-softmax attention + beta-gate + LN.
// Emits h as bf16 hi/lo planes for the HMMA proj.
// ============================================================================
__global__ __launch_bounds__(256) void attn_kernel(
    const float* __restrict__ Wbeta,
    const float* __restrict__ lng, const float* __restrict__ lnb)
{
    __shared__ float sWb[768];
    __shared__ float sg[256], sb[256];
    int t = threadIdx.x;
    for (int i = t; i < 768; i += 256) sWb[i] = Wbeta[i];
    if (t < 256) { sg[t] = lng[t]; sb[t] = lnb[t]; }
    __syncthreads();

    int warp = t >> 5, lane = t & 31;
    int node = blockIdx.x * 8 + warp;
    if (node >= NN) return;

    int c0 = lane * 8;
    const float* qp = g_buf + (size_t)node * QS + c0;
    float q[8];
    *(float4*)(q)     = *(const float4*)(qp);
    *(float4*)(q + 4) = *(const float4*)(qp + 4);
#pragma unroll
    for (int u = 0; u < 8; u++) q[u] *= 0.125f;

    float m = -1e30f, ssum = 0.f;
    float acc[8];
#pragma unroll
    for (int u = 0; u < 8; u++) acc[u] = 0.f;

    int e0 = g_start[node], e1 = g_start[node + 1];
    int src = (e0 < e1) ? g_esrc[e0] : 0;
    for (int e = e0; e < e1; e++) {
        const float* kp = g_buf + (size_t)src * QS + 256 + c0;
        float4 ka = *(const float4*)(kp);
        float4 kb = *(const float4*)(kp + 4);
        float4 va = *(const float4*)(kp + 256);
        float4 vb = *(const float4*)(kp + 260);
        int nsrc = (e + 1 < e1) ? g_esrc[e + 1] : 0;

        float p = q[0] * ka.x + q[1] * ka.y + q[2] * ka.z + q[3] * ka.w
                + q[4] * kb.x + q[5] * kb.y + q[6] * kb.z + q[7] * kb.w;
        p += __shfl_xor_sync(0xffffffffu, p, 1, 8);
        p += __shfl_xor_sync(0xffffffffu, p, 2, 8);
        p += __shfl_xor_sync(0xffffffffu, p, 4, 8);
        float mn = fmaxf(m, p);
        float sc = __expf(m - mn);
        float wgt = __expf(p - mn);
        m = mn;
        ssum = ssum * sc + wgt;
        acc[0] = acc[0] * sc + wgt * va.x;
        acc[1] = acc[1] * sc + wgt * va.y;
        acc[2] = acc[2] * sc + wgt * va.z;
        acc[3] = acc[3] * sc + wgt * va.w;
        acc[4] = acc[4] * sc + wgt * vb.x;
        acc[5] = acc[5] * sc + wgt * vb.y;
        acc[6] = acc[6] * sc + wgt * vb.z;
        acc[7] = acc[7] * sc + wgt * vb.w;
        src = nsrc;
    }
    float inv = 1.f / (ssum + 1e-16f);
    float outv[8];
#pragma unroll
    for (int u = 0; u < 8; u++) outv[u] = acc[u] * inv;

    const float* xp = g_buf + (size_t)node * QS + 768 + c0;
    float xr[8];
    *(float4*)(xr)     = *(const float4*)(xp);
    *(float4*)(xr + 4) = *(const float4*)(xp + 4);

    float part = 0.f;
#pragma unroll
    for (int u = 0; u < 8; u++) {
        int c = c0 + u;
        part += outv[u] * sWb[c] + xr[u] * sWb[256 + c] + (outv[u] - xr[u]) * sWb[512 + c];
    }
#pragma unroll
    for (int off = 16; off > 0; off >>= 1)
        part += __shfl_xor_sync(0xffffffffu, part, off);
    float beta = 1.f / (1.f + __expf(-part));

    float h[8], sum = 0.f, sq = 0.f;
#pragma unroll
    for (int u = 0; u < 8; u++) {
        h[u] = beta * xr[u] + (1.f - beta) * outv[u];
        sum += h[u];
        sq += h[u] * h[u];
    }
#pragma unroll
    for (int off = 16; off > 0; off >>= 1) {
        sum += __shfl_xor_sync(0xffffffffu, sum, off);
        sq  += __shfl_xor_sync(0xffffffffu, sq, off);
    }
    float mu = sum * (1.f / 256.f);
    float var = sq * (1.f / 256.f) - mu * mu;
    float rstd = rsqrtf(var + 1e-5f);

    __nv_bfloat162 hh[4], hl[4];
#pragma unroll
    for (int u = 0; u < 4; u++) {
        int c = c0 + 2 * u;
        float o0 = (h[2 * u]     - mu) * rstd * sg[c]     + sb[c];
        float o1 = (h[2 * u + 1] - mu) * rstd * sg[c + 1] + sb[c + 1];
        split2(o0, o1, hh[u], hl[u]);
    }
    *(uint4*)(g_hhi + (size_t)node * 256 + c0) = *(uint4*)hh;
    *(uint4*)(g_hlo + (size_t)node * 256 + c0) = *(uint4*)hl;
}

// ============================================================================
// Kernel 4 (HMMA + ldmatrix): out[n,64] = relu(h @ Wp^T + bp + x)
// 128 rows/block, 8 warps (warp = 16 rows x 64 cols). K=256 in 4 chunks of 64.
// ============================================================================
__global__ __launch_bounds__(256) void gemm_proj_mma(
    const float* __restrict__ x,
    const float* __restrict__ Wp, const float* __restrict__ bp,
    float* __restrict__ out)
{
    extern __shared__ __nv_bfloat16 sm[];
    __nv_bfloat16* Hhi = sm;
    __nv_bfloat16* Hlo = sm + 128 * AST;
    __nv_bfloat16* Phi = sm + 2 * 128 * AST;
    __nv_bfloat16* Plo = sm + 2 * 128 * AST + 64 * AST;
    float* sbias = (float*)(sm + 2 * 128 * AST + 2 * 64 * AST);

    int t = threadIdx.x;
    int row0 = blockIdx.x * 128;
    if (t < 64) sbias[t] = bp[t];

    int wid = t >> 5, lane = t & 31;
    int g = lane >> 2, tq = lane & 3;
    int r0 = wid * 16;

    int aoff = (r0 + (lane & 15)) * AST + (lane >> 4) * 8;
    uint32_t aHiB = smem_u32(Hhi) + aoff * 2;
    uint32_t aLoB = smem_u32(Hlo) + aoff * 2;
    int bcol = ((lane >> 4) << 3) + (lane & 7);
    int bkh = ((lane >> 3) & 1) * 8;
    uint32_t bHiB = smem_u32(Phi) + (bcol * AST + bkh) * 2;
    uint32_t bLoB = smem_u32(Plo) + (bcol * AST + bkh) * 2;

    float acc[8][4];
#pragma unroll
    for (int nt = 0; nt < 8; nt++)
#pragma unroll
        for (int j = 0; j < 4; j++) acc[nt][j] = 0.f;

    for (int kc = 0; kc < 256; kc += 64) {
        __syncthreads();
        // load H chunk [128 rows x 64 k] bf16 hi/lo (direct copy, no convert)
#pragma unroll
        for (int i = 0; i < 4; i++) {
            int u = t + i * 256;
            int r = u >> 3, qd = u & 7;
            int rg = row0 + r;
            uint4 vh = make_uint4(0, 0, 0, 0), vl = make_uint4(0, 0, 0, 0);
            if (rg < NN) {
                vh = *(const uint4*)(g_hhi + (size_t)rg * 256 + kc + qd * 8);
                vl = *(const uint4*)(g_hlo + (size_t)rg * 256 + kc + qd * 8);
            }
            *(uint4*)(Hhi + r * AST + qd * 8) = vh;
            *(uint4*)(Hlo + r * AST + qd * 8) = vl;
        }
        // load + split W chunk [64 cols x 64 k]
#pragma unroll
        for (int i = 0; i < 4; i++) {
            int u = t + i * 256;
            int r = u >> 4, qd = u & 15;
            float4 w4 = *(const float4*)(Wp + (size_t)r * 256 + kc + qd * 4);
            __nv_bfloat162 h0, l0, h1, l1;
            split2(w4.x, w4.y, h0, l0);
            split2(w4.z, w4.w, h1, l1);
            int so = r * AST + qd * 4;
            *(__nv_bfloat162*)(Phi + so) = h0;  *(__nv_bfloat162*)(Phi + so + 2) = h1;
            *(__nv_bfloat162*)(Plo + so) = l0;  *(__nv_bfloat162*)(Plo + so + 2) = l1;
        }
        __syncthreads();

#pragma unroll
        for (int ks = 0; ks < 4; ks++) {
            uint32_t kbB = ks * 32;
            uint32_t ahi[4], alo[4];
            LDMX4(ahi, aHiB + kbB);
            LDMX4(alo, aLoB + kbB);
#pragma unroll
            for (int ntg = 0; ntg < 4; ntg++) {
                uint32_t cgB = (uint32_t)(ntg * 16 * AST * 2);
                uint32_t bh[4], bl[4];
                LDMX4(bh, bHiB + cgB + kbB);
                LDMX4(bl, bLoB + cgB + kbB);
                mma16816(acc[2 * ntg],     ahi, bh);
                mma16816(acc[2 * ntg + 1], ahi, bh + 2);
                mma16816(acc[2 * ntg],     ahi, bl);
                mma16816(acc[2 * ntg + 1], ahi, bl + 2);
                mma16816(acc[2 * ntg],     alo, bh);
                mma16816(acc[2 * ntg + 1], alo, bh + 2);
            }
        }
    }

    int rA = row0 + r0 + g;
    int rB = rA + 8;
#pragma unroll
    for (int nt = 0; nt < 8; nt++) {
        int lc = nt * 8 + tq * 2;
        float b0 = sbias[lc], b1 = sbias[lc + 1];
        if (rA < NN) {
            float2 xv = *(const float2*)(x + (size_t)rA * 64 + lc);
            *(float2*)(out + (size_t)rA * 64 + lc) =
                make_float2(fmaxf(acc[nt][0] + b0 + xv.x, 0.f), fmaxf(acc[nt][1] + b1 + xv.y, 0.f));
        }
        if (rB < NN) {
            float2 xv = *(const float2*)(x + (size_t)rB * 64 + lc);
            *(float2*)(out + (size_t)rB * 64 + lc) =
                make_float2(fmaxf(acc[nt][2] + b0 + xv.x, 0.f), fmaxf(acc[nt][3] + b1 + xv.y, 0.f));
        }
    }
}

// ============================================================================
extern "C" void kernel_launch(void* const* d_in, const int* in_sizes, int n_in,
                              void* d_out, int out_size)
{
    const float* x     = (const float*)d_in[0];
    const int*   ei    = (const int*)d_in[1];
    const float* Wq    = (const float*)d_in[2];
    const float* bq    = (const float*)d_in[3];
    const float* Wk    = (const float*)d_in[4];
    const float* bk    = (const float*)d_in[5];
    const float* Wv    = (const float*)d_in[6];
    const float* bv    = (const float*)d_in[7];
    const float* Wsk   = (const float*)d_in[8];
    const float* bsk   = (const float*)d_in[9];
    const float* Wbeta = (const float*)d_in[10];
    const float* lng   = (const float*)d_in[11];
    const float* lnb   = (const float*)d_in[12];
    const float* Wp    = (const float*)d_in[13];
    const float* bp    = (const float*)d_in[14];
    float* out = (float*)d_out;

    static int attr_set = 0;
    if (!attr_set) {
        cudaFuncSetAttribute(gemm_qkvs_mma,
                             cudaFuncAttributeMaxDynamicSharedMemorySize, QKV_SMEM_BYTES);
        cudaFuncSetAttribute(gemm_proj_mma,
                             cudaFuncAttributeMaxDynamicSharedMemorySize, PROJ_SMEM_BYTES);
        attr_set = 1;
    }

    void* dcp = nullptr;
    cudaGetSymbolAddress(&dcp, g_degcur);
    cudaMemsetAsync(dcp, 0, 2 * NN * sizeof(int));

    hist_kernel<<<2500, 256>>>(ei);
    scan_kernel<<<1, 1024>>>();
    scatter_kernel<<<2500, 256>>>(ei);
    gemm_qkvs_mma<<<dim3(8, 391), 256, QKV_SMEM_BYTES>>>(x, Wq, bq, Wk, bk, Wv, bv, Wsk, bsk);
    attn_kernel<<<6250, 256>>>(Wbeta, lng, lnb);
    gemm_proj_mma<<<391, 256, PROJ_SMEM_BYTES>>>(x, Wp, bp, out);
}

// round 10
// speedup vs baseline: 1.4688x; 1.0128x over previous
#include <cuda_runtime.h>
#include <cuda_bf16.h>
#include <cstdint>

#define NN 50000
#define EE 640000
#define QS 1024          // row stride of fused qkv/skip buffer

// ---- scratch (static device globals: allocation-free rule) ----
__device__ __align__(16) float g_buf[(size_t)NN * QS];            // [q|k|v|x_r], 204.8MB
__device__ __align__(16) __nv_bfloat16 g_hhi[(size_t)NN * 256];   // h hi plane, 25.6MB
__device__ __align__(16) __nv_bfloat16 g_hlo[(size_t)NN * 256];   // h lo plane, 25.6MB
__device__ int g_degcur[2 * NN];
__device__ int g_start[NN + 1];
__device__ int g_esrc[EE];

// ---- warp-level bf16 MMA (m16n8k16, fp32 accum) ----
__device__ __forceinline__ void mma16816(float* c, const uint32_t* a, const uint32_t* b) {
    asm volatile(
        "mma.sync.aligned.m16n8k16.row.col.f32.bf16.bf16.f32 "
        "{%0,%1,%2,%3}, {%4,%5,%6,%7}, {%8,%9}, {%0,%1,%2,%3};\n"
        : "+f"(c[0]), "+f"(c[1]), "+f"(c[2]), "+f"(c[3])
        : "r"(a[0]), "r"(a[1]), "r"(a[2]), "r"(a[3]), "r"(b[0]), "r"(b[1]));
}
#define LDMX4(r, addr)                                                            \
    asm volatile("ldmatrix.sync.aligned.m8n8.x4.shared.b16 {%0,%1,%2,%3}, [%4];"  \
        : "=r"((r)[0]), "=r"((r)[1]), "=r"((r)[2]), "=r"((r)[3]) : "r"(addr))

__device__ __forceinline__ uint32_t smem_u32(const void* p) {
    uint32_t a;
    asm("{ .reg .u64 t; cvta.to.shared.u64 t, %1; cvt.u32.u64 %0, t; }" : "=r"(a) : "l"(p));
    return a;
}
// split float -> (hi, lo) bf16 pair packed as bf162
__device__ __forceinline__ void split2(float x0, float x1, __nv_bfloat162& hi, __nv_bfloat162& lo) {
    hi = __floats2bfloat162_rn(x0, x1);
    lo = __floats2bfloat162_rn(x0 - __bfloat162float(__low2bfloat16(hi)),
                               x1 - __bfloat162float(__high2bfloat16(hi)));
}

#define AST 72   // smem row stride in bf16 (conflict-free for ldmatrix)

// gemm_qkvs smem: Ahi|Alo|Whi|Wlo each 128*AST bf16, + 128 floats bias
#define QKV_SMEM_BYTES (4 * 128 * AST * 2 + 512)
// proj smem: Hhi|Hlo 128*AST + Whi|Wlo 64*AST (bf16) + 64 floats bias
#define PROJ_SMEM_BYTES ((2 * 128 * AST + 2 * 64 * AST) * 2 + 256)

// ============================================================================
// Kernel 1 (HMMA + ldmatrix): g_buf[n,1024] = x[n,64] @ [Wq|Wk|Wv|Wskip]^T + b
// 128x128 tile/block. Warp grid 4x2: warp = 32 rows x 64 cols
// (48 LDSM.x4/warp vs 72 for the 16x128 layout -> L1 traffic -33%).
// bf16 hi/lo split, 3 accumulating terms (hi*hi + hi*lo + lo*hi).
// ============================================================================
__global__ __launch_bounds__(256) void gemm_qkvs_mma(
    const float* __restrict__ x,
    const float* __restrict__ Wq, const float* __restrict__ bq,
    const float* __restrict__ Wk, const float* __restrict__ bk,
    const float* __restrict__ Wv, const float* __restrict__ bv,
    const float* __restrict__ Wsk, const float* __restrict__ bsk)
{
    extern __shared__ __nv_bfloat16 sm[];
    __nv_bfloat16* Ahi = sm;
    __nv_bfloat16* Alo = sm + 128 * AST;
    __nv_bfloat16* Whi = sm + 2 * 128 * AST;
    __nv_bfloat16* Wlo = sm + 3 * 128 * AST;
    float* sbias = (float*)(sm + 4 * 128 * AST);

    int t = threadIdx.x;
    int bx = blockIdx.x, by = blockIdx.y;
    int c0 = bx * 128;
    int which = c0 >> 8, dbase = c0 & 255;
    const float* W = (which == 0) ? Wq : (which == 1) ? Wk : (which == 2) ? Wv : Wsk;
    const float* B = (which == 0) ? bq : (which == 1) ? bk : (which == 2) ? bv : bsk;
    int row0 = by * 128;

    if (t < 128) sbias[t] = B[dbase + t];

    // load + hi/lo split-convert: A = x tile [128,64], B = W tile [128,64]
#pragma unroll
    for (int i = 0; i < 8; i++) {
        int idx = t + i * 256;
        int r = idx >> 4, qd = idx & 15;
        int so = r * AST + qd * 4;
        float4 v = make_float4(0.f, 0.f, 0.f, 0.f);
        int rg = row0 + r;
        if (rg < NN) v = *(const float4*)(x + (size_t)rg * 64 + qd * 4);
        __nv_bfloat162 h0, l0, h1, l1;
        split2(v.x, v.y, h0, l0);
        split2(v.z, v.w, h1, l1);
        *(__nv_bfloat162*)(Ahi + so) = h0;  *(__nv_bfloat162*)(Ahi + so + 2) = h1;
        *(__nv_bfloat162*)(Alo + so) = l0;  *(__nv_bfloat162*)(Alo + so + 2) = l1;
        float4 w4 = *(const float4*)(W + (size_t)(dbase + r) * 64 + qd * 4);
        split2(w4.x, w4.y, h0, l0);
        split2(w4.z, w4.w, h1, l1);
        *(__nv_bfloat162*)(Whi + so) = h0;  *(__nv_bfloat162*)(Whi + so + 2) = h1;
        *(__nv_bfloat162*)(Wlo + so) = l0;  *(__nv_bfloat162*)(Wlo + so + 2) = l1;
    }
    __syncthreads();

    int wid = t >> 5, lane = t & 31;
    int g = lane >> 2, tq = lane & 3;
    int r0 = (wid & 3) * 32;          // warp row base (4 m-groups of 32)
    int cw = (wid >> 2) * 64;         // warp col base (2 n-groups of 64)

    // ldmatrix lane-address bases
    int aoff0 = (r0 + (lane & 15)) * AST + (lane >> 4) * 8;
    int aoff1 = (r0 + 16 + (lane & 15)) * AST + (lane >> 4) * 8;
    uint32_t aHi0 = smem_u32(Ahi) + aoff0 * 2, aHi1 = smem_u32(Ahi) + aoff1 * 2;
    uint32_t aLo0 = smem_u32(Alo) + aoff0 * 2, aLo1 = smem_u32(Alo) + aoff1 * 2;
    int bcol = cw + ((lane >> 4) << 3) + (lane & 7);
    int bkh = ((lane >> 3) & 1) * 8;
    uint32_t bHiB = smem_u32(Whi) + (bcol * AST + bkh) * 2;
    uint32_t bLoB = smem_u32(Wlo) + (bcol * AST + bkh) * 2;

    float acc[2][8][4];
#pragma unroll
    for (int mt = 0; mt < 2; mt++)
#pragma unroll
        for (int nt = 0; nt < 8; nt++)
#pragma unroll
            for (int j = 0; j < 4; j++) acc[mt][nt][j] = 0.f;

#pragma unroll
    for (int ks = 0; ks < 4; ks++) {
        uint32_t kbB = ks * 32;  // 16 bf16 = 32 bytes
        uint32_t ahi[2][4], alo[2][4];
        LDMX4(ahi[0], aHi0 + kbB);
        LDMX4(ahi[1], aHi1 + kbB);
        LDMX4(alo[0], aLo0 + kbB);
        LDMX4(alo[1], aLo1 + kbB);
#pragma unroll
        for (int ntg = 0; ntg < 4; ntg++) {
            uint32_t cgB = (uint32_t)(ntg * 16 * AST * 2);
            uint32_t bh[4], bl[4];
            LDMX4(bh, bHiB + cgB + kbB);
            LDMX4(bl, bLoB + cgB + kbB);
#pragma unroll
            for (int mt = 0; mt < 2; mt++) {
                mma16816(acc[mt][2 * ntg],     ahi[mt], bh);
                mma16816(acc[mt][2 * ntg + 1], ahi[mt], bh + 2);
                mma16816(acc[mt][2 * ntg],     ahi[mt], bl);
                mma16816(acc[mt][2 * ntg + 1], ahi[mt], bl + 2);
                mma16816(acc[mt][2 * ntg],     alo[mt], bh);
                mma16816(acc[mt][2 * ntg + 1], alo[mt], bh + 2);
            }
        }
    }

#pragma unroll
    for (int mt = 0; mt < 2; mt++) {
        int rA = row0 + r0 + mt * 16 + g;
        int rB = rA + 8;
#pragma unroll
        for (int nt = 0; nt < 8; nt++) {
            int lc = cw + nt * 8 + tq * 2;
            float b0 = sbias[lc], b1 = sbias[lc + 1];
            if (rA < NN)
                *(float2*)(g_buf + (size_t)rA * QS + c0 + lc) =
                    make_float2(acc[mt][nt][0] + b0, acc[mt][nt][1] + b1);
            if (rB < NN)
                *(float2*)(g_buf + (size_t)rB * QS + c0 + lc) =
                    make_float2(acc[mt][nt][2] + b0, acc[mt][nt][3] + b1);
        }
    }
}

// ============================================================================
// CSR build: histogram -> exclusive scan (single block) -> scatter
// ============================================================================
__global__ __launch_bounds__(256) void hist_kernel(const int* __restrict__ ei)
{
    int e = blockIdx.x * 256 + threadIdx.x;
    if (e < EE) atomicAdd(&g_degcur[ei[EE + e]], 1);
}

__global__ __launch_bounds__(1024) void scan_kernel()
{
    __shared__ int wsum[32];
    __shared__ int carryS;
    int t = threadIdx.x;
    int lane = t & 31, w = t >> 5;
    if (t == 0) carryS = 0;
    __syncthreads();
    for (int base = 0; base < NN; base += 1024) {
        int i = base + t;
        int v = (i < NN) ? g_degcur[i] : 0;
        int xv = v;
#pragma unroll
        for (int off = 1; off < 32; off <<= 1) {
            int u = __shfl_up_sync(0xffffffffu, xv, off);
            if (lane >= off) xv += u;
        }
        if (lane == 31) wsum[w] = xv;
        __syncthreads();
        if (w == 0) {
            int y = wsum[lane];
#pragma unroll
            for (int off = 1; off < 32; off <<= 1) {
                int u = __shfl_up_sync(0xffffffffu, y, off);
                if (lane >= off) y += u;
            }
            wsum[lane] = y;
        }
        __syncthreads();
        int incl = xv + (w ? wsum[w - 1] : 0);
        int c = carryS;
        if (i < NN) g_start[i] = c + incl - v;
        __syncthreads();
        if (t == 0) carryS = c + wsum[31];
        __syncthreads();
    }
    if (t == 0) g_start[NN] = carryS;
}

__global__ __launch_bounds__(256) void scatter_kernel(const int* __restrict__ ei)
{
    int e = blockIdx.x * 256 + threadIdx.x;
    if (e < EE) {
        int d = ei[EE + e];
        int s = ei[e];
        int pos = g_start[d] + atomicAdd(&g_degcur[NN + d], 1);
        g_esrc[pos] = s;
    }
}

// ============================================================================
// Kernel 3: warp-per-dst online-softmax attention + beta-gate + LN.
// Emits h as bf16 hi/lo planes for the HMMA proj.
// ============================================================================
__global__ __launch_bounds__(256) void attn_kernel(
    const float* __restrict__ Wbeta,
    const float* __restrict__ lng, const float* __restrict__ lnb)
{
    __shared__ float sWb[768];
    __shared__ float sg[256], sb[256];
    int t = threadIdx.x;
    for (int i = t; i < 768; i += 256) sWb[i] = Wbeta[i];
    if (t < 256) { sg[t] = lng[t]; sb[t] = lnb[t]; }
    __syncthreads();

    int warp = t >> 5, lane = t & 31;
    int node = blockIdx.x * 8 + warp;
    if (node >= NN) return;

    int c0 = lane * 8;
    const float* qp = g_buf + (size_t)node * QS + c0;
    float q[8];
    *(float4*)(q)     = *(const float4*)(qp);
    *(float4*)(q + 4) = *(const float4*)(qp + 4);
#pragma unroll
    for (int u = 0; u < 8; u++) q[u] *= 0.125f;

    float m = -1e30f, ssum = 0.f;
    float acc[8];
#pragma unroll
    for (int u = 0; u < 8; u++) acc[u] = 0.f;

    int e0 = g_start[node], e1 = g_start[node + 1];
    int src = (e0 < e1) ? g_esrc[e0] : 0;
    for (int e = e0; e < e1; e++) {
        const float* kp = g_buf + (size_t)src * QS + 256 + c0;
        float4 ka = *(const float4*)(kp);
        float4 kb = *(const float4*)(kp + 4);
        float4 va = *(const float4*)(kp + 256);
        float4 vb = *(const float4*)(kp + 260);
        int nsrc = (e + 1 < e1) ? g_esrc[e + 1] : 0;

        float p = q[0] * ka.x + q[1] * ka.y + q[2] * ka.z + q[3] * ka.w
                + q[4] * kb.x + q[5] * kb.y + q[6] * kb.z + q[7] * kb.w;
        p += __shfl_xor_sync(0xffffffffu, p, 1, 8);
        p += __shfl_xor_sync(0xffffffffu, p, 2, 8);
        p += __shfl_xor_sync(0xffffffffu, p, 4, 8);
        float mn = fmaxf(m, p);
        float sc = __expf(m - mn);
        float wgt = __expf(p - mn);
        m = mn;
        ssum = ssum * sc + wgt;
        acc[0] = acc[0] * sc + wgt * va.x;
        acc[1] = acc[1] * sc + wgt * va.y;
        acc[2] = acc[2] * sc + wgt * va.z;
        acc[3] = acc[3] * sc + wgt * va.w;
        acc[4] = acc[4] * sc + wgt * vb.x;
        acc[5] = acc[5] * sc + wgt * vb.y;
        acc[6] = acc[6] * sc + wgt * vb.z;
        acc[7] = acc[7] * sc + wgt * vb.w;
        src = nsrc;
    }
    float inv = 1.f / (ssum + 1e-16f);
    float outv[8];
#pragma unroll
    for (int u = 0; u < 8; u++) outv[u] = acc[u] * inv;

    const float* xp = g_buf + (size_t)node * QS + 768 + c0;
    float xr[8];
    *(float4*)(xr)     = *(const float4*)(xp);
    *(float4*)(xr + 4) = *(const float4*)(xp + 4);

    float part = 0.f;
#pragma unroll
    for (int u = 0; u < 8; u++) {
        int c = c0 + u;
        part += outv[u] * sWb[c] + xr[u] * sWb[256 + c] + (outv[u] - xr[u]) * sWb[512 + c];
    }
#pragma unroll
    for (int off = 16; off > 0; off >>= 1)
        part += __shfl_xor_sync(0xffffffffu, part, off);
    float beta = 1.f / (1.f + __expf(-part));

    float h[8], sum = 0.f, sq = 0.f;
#pragma unroll
    for (int u = 0; u < 8; u++) {
        h[u] = beta * xr[u] + (1.f - beta) * outv[u];
        sum += h[u];
        sq += h[u] * h[u];
    }
#pragma unroll
    for (int off = 16; off > 0; off >>= 1) {
        sum += __shfl_xor_sync(0xffffffffu, sum, off);
        sq  += __shfl_xor_sync(0xffffffffu, sq, off);
    }
    float mu = sum * (1.f / 256.f);
    float var = sq * (1.f / 256.f) - mu * mu;
    float rstd = rsqrtf(var + 1e-5f);

    __nv_bfloat162 hh[4], hl[4];
#pragma unroll
    for (int u = 0; u < 4; u++) {
        int c = c0 + 2 * u;
        float o0 = (h[2 * u]     - mu) * rstd * sg[c]     + sb[c];
        float o1 = (h[2 * u + 1] - mu) * rstd * sg[c + 1] + sb[c + 1];
        split2(o0, o1, hh[u], hl[u]);
    }
    *(uint4*)(g_hhi + (size_t)node * 256 + c0) = *(uint4*)hh;
    *(uint4*)(g_hlo + (size_t)node * 256 + c0) = *(uint4*)hl;
}

// ============================================================================
// Kernel 4 (HMMA + ldmatrix): out[n,64] = relu(h @ Wp^T + bp + x)
// 128 rows/block, 8 warps (warp = 16 rows x 64 cols). K=256 in 4 chunks of 64.
// ============================================================================
__global__ __launch_bounds__(256) void gemm_proj_mma(
    const float* __restrict__ x,
    const float* __restrict__ Wp, const float* __restrict__ bp,
    float* __restrict__ out)
{
    extern __shared__ __nv_bfloat16 sm[];
    __nv_bfloat16* Hhi = sm;
    __nv_bfloat16* Hlo = sm + 128 * AST;
    __nv_bfloat16* Phi = sm + 2 * 128 * AST;
    __nv_bfloat16* Plo = sm + 2 * 128 * AST + 64 * AST;
    float* sbias = (float*)(sm + 2 * 128 * AST + 2 * 64 * AST);

    int t = threadIdx.x;
    int row0 = blockIdx.x * 128;
    if (t < 64) sbias[t] = bp[t];

    int wid = t >> 5, lane = t & 31;
    int g = lane >> 2, tq = lane & 3;
    int r0 = wid * 16;

    int aoff = (r0 + (lane & 15)) * AST + (lane >> 4) * 8;
    uint32_t aHiB = smem_u32(Hhi) + aoff * 2;
    uint32_t aLoB = smem_u32(Hlo) + aoff * 2;
    int bcol = ((lane >> 4) << 3) + (lane & 7);
    int bkh = ((lane >> 3) & 1) * 8;
    uint32_t bHiB = smem_u32(Phi) + (bcol * AST + bkh) * 2;
    uint32_t bLoB = smem_u32(Plo) + (bcol * AST + bkh) * 2;

    float acc[8][4];
#pragma unroll
    for (int nt = 0; nt < 8; nt++)
#pragma unroll
        for (int j = 0; j < 4; j++) acc[nt][j] = 0.f;

    for (int kc = 0; kc < 256; kc += 64) {
        __syncthreads();
#pragma unroll
        for (int i = 0; i < 4; i++) {
            int u = t + i * 256;
            int r = u >> 3, qd = u & 7;
            int rg = row0 + r;
            uint4 vh = make_uint4(0, 0, 0, 0), vl = make_uint4(0, 0, 0, 0);
            if (rg < NN) {
                vh = *(const uint4*)(g_hhi + (size_t)rg * 256 + kc + qd * 8);
                vl = *(const uint4*)(g_hlo + (size_t)rg * 256 + kc + qd * 8);
            }
            *(uint4*)(Hhi + r * AST + qd * 8) = vh;
            *(uint4*)(Hlo + r * AST + qd * 8) = vl;
        }
#pragma unroll
        for (int i = 0; i < 4; i++) {
            int u = t + i * 256;
            int r = u >> 4, qd = u & 15;
            float4 w4 = *(const float4*)(Wp + (size_t)r * 256 + kc + qd * 4);
            __nv_bfloat162 h0, l0, h1, l1;
            split2(w4.x, w4.y, h0, l0);
            split2(w4.z, w4.w, h1, l1);
            int so = r * AST + qd * 4;
            *(__nv_bfloat162*)(Phi + so) = h0;  *(__nv_bfloat162*)(Phi + so + 2) = h1;
            *(__nv_bfloat162*)(Plo + so) = l0;  *(__nv_bfloat162*)(Plo + so + 2) = l1;
        }
        __syncthreads();

#pragma unroll
        for (int ks = 0; ks < 4; ks++) {
            uint32_t kbB = ks * 32;
            uint32_t ahi[4], alo[4];
            LDMX4(ahi, aHiB + kbB);
            LDMX4(alo, aLoB + kbB);
#pragma unroll
            for (int ntg = 0; ntg < 4; ntg++) {
                uint32_t cgB = (uint32_t)(ntg * 16 * AST * 2);
                uint32_t bh[4], bl[4];
                LDMX4(bh, bHiB + cgB + kbB);
                LDMX4(bl, bLoB + cgB + kbB);
                mma16816(acc[2 * ntg],     ahi, bh);
                mma16816(acc[2 * ntg + 1], ahi, bh + 2);
                mma16816(acc[2 * ntg],     ahi, bl);
                mma16816(acc[2 * ntg + 1], ahi, bl + 2);
                mma16816(acc[2 * ntg],     alo, bh);
                mma16816(acc[2 * ntg + 1], alo, bh + 2);
            }
        }
    }

    int rA = row0 + r0 + g;
    int rB = rA + 8;
#pragma unroll
    for (int nt = 0; nt < 8; nt++) {
        int lc = nt * 8 + tq * 2;
        float b0 = sbias[lc], b1 = sbias[lc + 1];
        if (rA < NN) {
            float2 xv = *(const float2*)(x + (size_t)rA * 64 + lc);
            *(float2*)(out + (size_t)rA * 64 + lc) =
                make_float2(fmaxf(acc[nt][0] + b0 + xv.x, 0.f), fmaxf(acc[nt][1] + b1 + xv.y, 0.f));
        }
        if (rB < NN) {
            float2 xv = *(const float2*)(x + (size_t)rB * 64 + lc);
            *(float2*)(out + (size_t)rB * 64 + lc) =
                make_float2(fmaxf(acc[nt][2] + b0 + xv.x, 0.f), fmaxf(acc[nt][3] + b1 + xv.y, 0.f));
        }
    }
}

// ============================================================================
extern "C" void kernel_launch(void* const* d_in, const int* in_sizes, int n_in,
                              void* d_out, int out_size)
{
    const float* x     = (const float*)d_in[0];
    const int*   ei    = (const int*)d_in[1];
    const float* Wq    = (const float*)d_in[2];
    const float* bq    = (const float*)d_in[3];
    const float* Wk    = (const float*)d_in[4];
    const float* bk    = (const float*)d_in[5];
    const float* Wv    = (const float*)d_in[6];
    const float* bv    = (const float*)d_in[7];
    const float* Wsk   = (const float*)d_in[8];
    const float* bsk   = (const float*)d_in[9];
    const float* Wbeta = (const float*)d_in[10];
    const float* lng   = (const float*)d_in[11];
    const float* lnb   = (const float*)d_in[12];
    const float* Wp    = (const float*)d_in[13];
    const float* bp    = (const float*)d_in[14];
    float* out = (float*)d_out;

    static int attr_set = 0;
    if (!attr_set) {
        cudaFuncSetAttribute(gemm_qkvs_mma,
                             cudaFuncAttributeMaxDynamicSharedMemorySize, QKV_SMEM_BYTES);
        cudaFuncSetAttribute(gemm_proj_mma,
                             cudaFuncAttributeMaxDynamicSharedMemorySize, PROJ_SMEM_BYTES);
        attr_set = 1;
    }

    void* dcp = nullptr;
    cudaGetSymbolAddress(&dcp, g_degcur);
    cudaMemsetAsync(dcp, 0, 2 * NN * sizeof(int));

    hist_kernel<<<2500, 256>>>(ei);
    scan_kernel<<<1, 1024>>>();
    scatter_kernel<<<2500, 256>>>(ei);
    gemm_qkvs_mma<<<dim3(8, 391), 256, QKV_SMEM_BYTES>>>(x, Wq, bq, Wk, bk, Wv, bv, Wsk, bsk);
    attn_kernel<<<6250, 256>>>(Wbeta, lng, lnb);
    gemm_proj_mma<<<391, 256, PROJ_SMEM_BYTES>>>(x, Wp, bp, out);
}

// round 11
// speedup vs baseline: 1.7654x; 1.2019x over previous
#include <cuda_runtime.h>
#include <cuda_bf16.h>
#include <cstdint>

#define NN 50000
#define EE 640000

// ---- scratch (static device globals: allocation-free rule) ----
__device__ __align__(16) float g_buf[(size_t)NN * 512];           // [q|x_r] fp32, 102.4MB
__device__ __align__(16) __nv_bfloat16 g_kv[(size_t)NN * 512];    // [k|v] bf16, 51.2MB (L2-resident)
__device__ __align__(16) __nv_bfloat16 g_hhi[(size_t)NN * 256];   // h hi plane, 25.6MB
__device__ __align__(16) __nv_bfloat16 g_hlo[(size_t)NN * 256];   // h lo plane, 25.6MB
__device__ int g_degcur[2 * NN];
__device__ int g_start[NN + 1];
__device__ int g_esrc[EE];

// ---- warp-level bf16 MMA (m16n8k16, fp32 accum) ----
__device__ __forceinline__ void mma16816(float* c, const uint32_t* a, const uint32_t* b) {
    asm volatile(
        "mma.sync.aligned.m16n8k16.row.col.f32.bf16.bf16.f32 "
        "{%0,%1,%2,%3}, {%4,%5,%6,%7}, {%8,%9}, {%0,%1,%2,%3};\n"
        : "+f"(c[0]), "+f"(c[1]), "+f"(c[2]), "+f"(c[3])
        : "r"(a[0]), "r"(a[1]), "r"(a[2]), "r"(a[3]), "r"(b[0]), "r"(b[1]));
}
#define LDMX4(r, addr)                                                            \
    asm volatile("ldmatrix.sync.aligned.m8n8.x4.shared.b16 {%0,%1,%2,%3}, [%4];"  \
        : "=r"((r)[0]), "=r"((r)[1]), "=r"((r)[2]), "=r"((r)[3]) : "r"(addr))

__device__ __forceinline__ uint32_t smem_u32(const void* p) {
    uint32_t a;
    asm("{ .reg .u64 t; cvta.to.shared.u64 t, %1; cvt.u32.u64 %0, t; }" : "=r"(a) : "l"(p));
    return a;
}
// split float -> (hi, lo) bf16 pair packed as bf162
__device__ __forceinline__ void split2(float x0, float x1, __nv_bfloat162& hi, __nv_bfloat162& lo) {
    hi = __floats2bfloat162_rn(x0, x1);
    lo = __floats2bfloat162_rn(x0 - __bfloat162float(__low2bfloat16(hi)),
                               x1 - __bfloat162float(__high2bfloat16(hi)));
}
__device__ __forceinline__ float2 bf2f(uint32_t u) {
    __nv_bfloat162 b = *(__nv_bfloat162*)&u;
    return __bfloat1622float2(b);
}

#define AST 72   // smem row stride in bf16 (conflict-free for ldmatrix)

// gemm_qkvs smem: Ahi|Alo|Whi|Wlo each 128*AST bf16, + 128 floats bias
#define QKV_SMEM_BYTES (4 * 128 * AST * 2 + 512)
// proj smem: Hhi|Hlo 128*AST + Whi|Wlo 64*AST (bf16) + 64 floats bias
#define PROJ_SMEM_BYTES ((2 * 128 * AST + 2 * 64 * AST) * 2 + 256)

// ============================================================================
// Kernel 1 (HMMA + ldmatrix): qkv+skip GEMM. q,x_r -> g_buf fp32; k,v -> g_kv bf16.
// 128x128 tile/block, warp grid 4x2 (warp = 32 rows x 64 cols).
// bf16 hi/lo split, 3 accumulating terms.
// ============================================================================
__global__ __launch_bounds__(256) void gemm_qkvs_mma(
    const float* __restrict__ x,
    const float* __restrict__ Wq, const float* __restrict__ bq,
    const float* __restrict__ Wk, const float* __restrict__ bk,
    const float* __restrict__ Wv, const float* __restrict__ bv,
    const float* __restrict__ Wsk, const float* __restrict__ bsk)
{
    extern __shared__ __nv_bfloat16 sm[];
    __nv_bfloat16* Ahi = sm;
    __nv_bfloat16* Alo = sm + 128 * AST;
    __nv_bfloat16* Whi = sm + 2 * 128 * AST;
    __nv_bfloat16* Wlo = sm + 3 * 128 * AST;
    float* sbias = (float*)(sm + 4 * 128 * AST);

    int t = threadIdx.x;
    int bx = blockIdx.x, by = blockIdx.y;
    int c0 = bx * 128;
    int which = c0 >> 8, dbase = c0 & 255;
    const float* W = (which == 0) ? Wq : (which == 1) ? Wk : (which == 2) ? Wv : Wsk;
    const float* B = (which == 0) ? bq : (which == 1) ? bk : (which == 2) ? bv : bsk;
    int row0 = by * 128;

    if (t < 128) sbias[t] = B[dbase + t];

    // load + hi/lo split-convert: A = x tile [128,64], B = W tile [128,64]
#pragma unroll
    for (int i = 0; i < 8; i++) {
        int idx = t + i * 256;
        int r = idx >> 4, qd = idx & 15;
        int so = r * AST + qd * 4;
        float4 v = make_float4(0.f, 0.f, 0.f, 0.f);
        int rg = row0 + r;
        if (rg < NN) v = *(const float4*)(x + (size_t)rg * 64 + qd * 4);
        __nv_bfloat162 h0, l0, h1, l1;
        split2(v.x, v.y, h0, l0);
        split2(v.z, v.w, h1, l1);
        *(__nv_bfloat162*)(Ahi + so) = h0;  *(__nv_bfloat162*)(Ahi + so + 2) = h1;
        *(__nv_bfloat162*)(Alo + so) = l0;  *(__nv_bfloat162*)(Alo + so + 2) = l1;
        float4 w4 = *(const float4*)(W + (size_t)(dbase + r) * 64 + qd * 4);
        split2(w4.x, w4.y, h0, l0);
        split2(w4.z, w4.w, h1, l1);
        *(__nv_bfloat162*)(Whi + so) = h0;  *(__nv_bfloat162*)(Whi + so + 2) = h1;
        *(__nv_bfloat162*)(Wlo + so) = l0;  *(__nv_bfloat162*)(Wlo + so + 2) = l1;
    }
    __syncthreads();

    int wid = t >> 5, lane = t & 31;
    int g = lane >> 2, tq = lane & 3;
    int r0 = (wid & 3) * 32;
    int cw = (wid >> 2) * 64;

    int aoff0 = (r0 + (lane & 15)) * AST + (lane >> 4) * 8;
    int aoff1 = (r0 + 16 + (lane & 15)) * AST + (lane >> 4) * 8;
    uint32_t aHi0 = smem_u32(Ahi) + aoff0 * 2, aHi1 = smem_u32(Ahi) + aoff1 * 2;
    uint32_t aLo0 = smem_u32(Alo) + aoff0 * 2, aLo1 = smem_u32(Alo) + aoff1 * 2;
    int bcol = cw + ((lane >> 4) << 3) + (lane & 7);
    int bkh = ((lane >> 3) & 1) * 8;
    uint32_t bHiB = smem_u32(Whi) + (bcol * AST + bkh) * 2;
    uint32_t bLoB = smem_u32(Wlo) + (bcol * AST + bkh) * 2;

    float acc[2][8][4];
#pragma unroll
    for (int mt = 0; mt < 2; mt++)
#pragma unroll
        for (int nt = 0; nt < 8; nt++)
#pragma unroll
            for (int j = 0; j < 4; j++) acc[mt][nt][j] = 0.f;

#pragma unroll
    for (int ks = 0; ks < 4; ks++) {
        uint32_t kbB = ks * 32;
        uint32_t ahi[2][4], alo[2][4];
        LDMX4(ahi[0], aHi0 + kbB);
        LDMX4(ahi[1], aHi1 + kbB);
        LDMX4(alo[0], aLo0 + kbB);
        LDMX4(alo[1], aLo1 + kbB);
#pragma unroll
        for (int ntg = 0; ntg < 4; ntg++) {
            uint32_t cgB = (uint32_t)(ntg * 16 * AST * 2);
            uint32_t bh[4], bl[4];
            LDMX4(bh, bHiB + cgB + kbB);
            LDMX4(bl, bLoB + cgB + kbB);
#pragma unroll
            for (int mt = 0; mt < 2; mt++) {
                mma16816(acc[mt][2 * ntg],     ahi[mt], bh);
                mma16816(acc[mt][2 * ntg + 1], ahi[mt], bh + 2);
                mma16816(acc[mt][2 * ntg],     ahi[mt], bl);
                mma16816(acc[mt][2 * ntg + 1], ahi[mt], bl + 2);
                mma16816(acc[mt][2 * ntg],     alo[mt], bh);
                mma16816(acc[mt][2 * ntg + 1], alo[mt], bh + 2);
            }
        }
    }

    bool isf32 = (which == 0) || (which == 3);
    int f32off = (which == 0) ? 0 : 256;   // q at 0, x_r at 256 in g_buf
    int kvoff  = (which == 1) ? 0 : 256;   // k at 0, v at 256 in g_kv
#pragma unroll
    for (int mt = 0; mt < 2; mt++) {
        int rA = row0 + r0 + mt * 16 + g;
        int rB = rA + 8;
#pragma unroll
        for (int nt = 0; nt < 8; nt++) {
            int lc = cw + nt * 8 + tq * 2;
            float b0 = sbias[lc], b1 = sbias[lc + 1];
            int ch = dbase + lc;
            if (rA < NN) {
                if (isf32)
                    *(float2*)(g_buf + (size_t)rA * 512 + f32off + ch) =
                        make_float2(acc[mt][nt][0] + b0, acc[mt][nt][1] + b1);
                else
                    *(__nv_bfloat162*)(g_kv + (size_t)rA * 512 + kvoff + ch) =
                        __floats2bfloat162_rn(acc[mt][nt][0] + b0, acc[mt][nt][1] + b1);
            }
            if (rB < NN) {
                if (isf32)
                    *(float2*)(g_buf + (size_t)rB * 512 + f32off + ch) =
                        make_float2(acc[mt][nt][2] + b0, acc[mt][nt][3] + b1);
                else
                    *(__nv_bfloat162*)(g_kv + (size_t)rB * 512 + kvoff + ch) =
                        __floats2bfloat162_rn(acc[mt][nt][2] + b0, acc[mt][nt][3] + b1);
            }
        }
    }
}

// ============================================================================
// CSR build: histogram -> exclusive scan (single block) -> scatter
// ============================================================================
__global__ __launch_bounds__(256) void hist_kernel(const int* __restrict__ ei)
{
    int e = blockIdx.x * 256 + threadIdx.x;
    if (e < EE) atomicAdd(&g_degcur[ei[EE + e]], 1);
}

__global__ __launch_bounds__(1024) void scan_kernel()
{
    __shared__ int wsum[32];
    __shared__ int carryS;
    int t = threadIdx.x;
    int lane = t & 31, w = t >> 5;
    if (t == 0) carryS = 0;
    __syncthreads();
    for (int base = 0; base < NN; base += 1024) {
        int i = base + t;
        int v = (i < NN) ? g_degcur[i] : 0;
        int xv = v;
#pragma unroll
        for (int off = 1; off < 32; off <<= 1) {
            int u = __shfl_up_sync(0xffffffffu, xv, off);
            if (lane >= off) xv += u;
        }
        if (lane == 31) wsum[w] = xv;
        __syncthreads();
        if (w == 0) {
            int y = wsum[lane];
#pragma unroll
            for (int off = 1; off < 32; off <<= 1) {
                int u = __shfl_up_sync(0xffffffffu, y, off);
                if (lane >= off) y += u;
            }
            wsum[lane] = y;
        }
        __syncthreads();
        int incl = xv + (w ? wsum[w - 1] : 0);
        int c = carryS;
        if (i < NN) g_start[i] = c + incl - v;
        __syncthreads();
        if (t == 0) carryS = c + wsum[31];
        __syncthreads();
    }
    if (t == 0) g_start[NN] = carryS;
}

__global__ __launch_bounds__(256) void scatter_kernel(const int* __restrict__ ei)
{
    int e = blockIdx.x * 256 + threadIdx.x;
    if (e < EE) {
        int d = ei[EE + e];
        int s = ei[e];
        int pos = g_start[d] + atomicAdd(&g_degcur[NN + d], 1);
        g_esrc[pos] = s;
    }
}

// ============================================================================
// Kernel 3: warp-per-dst online-softmax attention + beta-gate + LN.
// k/v gathered as bf16 (16B each per lane) -> half the L2 traffic of fp32.
// Emits h as bf16 hi/lo planes for the HMMA proj.
// ============================================================================
__global__ __launch_bounds__(256) void attn_kernel(
    const float* __restrict__ Wbeta,
    const float* __restrict__ lng, const float* __restrict__ lnb)
{
    __shared__ float sWb[768];
    __shared__ float sg[256], sb[256];
    int t = threadIdx.x;
    for (int i = t; i < 768; i += 256) sWb[i] = Wbeta[i];
    if (t < 256) { sg[t] = lng[t]; sb[t] = lnb[t]; }
    __syncthreads();

    int warp = t >> 5, lane = t & 31;
    int node = blockIdx.x * 8 + warp;
    if (node >= NN) return;

    int c0 = lane * 8;
    const float* qp = g_buf + (size_t)node * 512 + c0;
    float q[8];
    *(float4*)(q)     = *(const float4*)(qp);
    *(float4*)(q + 4) = *(const float4*)(qp + 4);
#pragma unroll
    for (int u = 0; u < 8; u++) q[u] *= 0.125f;   // 1/sqrt(64)

    float m = -1e30f, ssum = 0.f;
    float acc[8];
#pragma unroll
    for (int u = 0; u < 8; u++) acc[u] = 0.f;

    int e0 = g_start[node], e1 = g_start[node + 1];
    int src = (e0 < e1) ? g_esrc[e0] : 0;
    for (int e = e0; e < e1; e++) {
        const __nv_bfloat16* kp = g_kv + (size_t)src * 512 + c0;
        uint4 kraw = *(const uint4*)(kp);         // 8 bf16 k
        uint4 vraw = *(const uint4*)(kp + 256);   // 8 bf16 v
        int nsrc = (e + 1 < e1) ? g_esrc[e + 1] : 0;

        float2 k0 = bf2f(kraw.x), k1 = bf2f(kraw.y), k2 = bf2f(kraw.z), k3 = bf2f(kraw.w);
        float p = q[0] * k0.x + q[1] * k0.y + q[2] * k1.x + q[3] * k1.y
                + q[4] * k2.x + q[5] * k2.y + q[6] * k3.x + q[7] * k3.y;
        p += __shfl_xor_sync(0xffffffffu, p, 1, 8);
        p += __shfl_xor_sync(0xffffffffu, p, 2, 8);
        p += __shfl_xor_sync(0xffffffffu, p, 4, 8);
        float mn = fmaxf(m, p);
        float sc = __expf(m - mn);
        float wgt = __expf(p - mn);
        m = mn;
        ssum = ssum * sc + wgt;
        float2 v0 = bf2f(vraw.x), v1 = bf2f(vraw.y), v2 = bf2f(vraw.z), v3 = bf2f(vraw.w);
        acc[0] = acc[0] * sc + wgt * v0.x;
        acc[1] = acc[1] * sc + wgt * v0.y;
        acc[2] = acc[2] * sc + wgt * v1.x;
        acc[3] = acc[3] * sc + wgt * v1.y;
        acc[4] = acc[4] * sc + wgt * v2.x;
        acc[5] = acc[5] * sc + wgt * v2.y;
        acc[6] = acc[6] * sc + wgt * v3.x;
        acc[7] = acc[7] * sc + wgt * v3.y;
        src = nsrc;
    }
    float inv = 1.f / (ssum + 1e-16f);
    float outv[8];
#pragma unroll
    for (int u = 0; u < 8; u++) outv[u] = acc[u] * inv;

    const float* xp = g_buf + (size_t)node * 512 + 256 + c0;
    float xr[8];
    *(float4*)(xr)     = *(const float4*)(xp);
    *(float4*)(xr + 4) = *(const float4*)(xp + 4);

    float part = 0.f;
#pragma unroll
    for (int u = 0; u < 8; u++) {
        int c = c0 + u;
        part += outv[u] * sWb[c] + xr[u] * sWb[256 + c] + (outv[u] - xr[u]) * sWb[512 + c];
    }
#pragma unroll
    for (int off = 16; off > 0; off >>= 1)
        part += __shfl_xor_sync(0xffffffffu, part, off);
    float beta = 1.f / (1.f + __expf(-part));

    float h[8], sum = 0.f, sq = 0.f;
#pragma unroll
    for (int u = 0; u < 8; u++) {
        h[u] = beta * xr[u] + (1.f - beta) * outv[u];
        sum += h[u];
        sq += h[u] * h[u];
    }
#pragma unroll
    for (int off = 16; off > 0; off >>= 1) {
        sum += __shfl_xor_sync(0xffffffffu, sum, off);
        sq  += __shfl_xor_sync(0xffffffffu, sq, off);
    }
    float mu = sum * (1.f / 256.f);
    float var = sq * (1.f / 256.f) - mu * mu;
    float rstd = rsqrtf(var + 1e-5f);

    __nv_bfloat162 hh[4], hl[4];
#pragma unroll
    for (int u = 0; u < 4; u++) {
        int c = c0 + 2 * u;
        float o0 = (h[2 * u]     - mu) * rstd * sg[c]     + sb[c];
        float o1 = (h[2 * u + 1] - mu) * rstd * sg[c + 1] + sb[c + 1];
        split2(o0, o1, hh[u], hl[u]);
    }
    *(uint4*)(g_hhi + (size_t)node * 256 + c0) = *(uint4*)hh;
    *(uint4*)(g_hlo + (size_t)node * 256 + c0) = *(uint4*)hl;
}

// ============================================================================
// Kernel 4 (HMMA + ldmatrix): out[n,64] = relu(h @ Wp^T + bp + x)
// ============================================================================
__global__ __launch_bounds__(256) void gemm_proj_mma(
    const float* __restrict__ x,
    const float* __restrict__ Wp, const float* __restrict__ bp,
    float* __restrict__ out)
{
    extern __shared__ __nv_bfloat16 sm[];
    __nv_bfloat16* Hhi = sm;
    __nv_bfloat16* Hlo = sm + 128 * AST;
    __nv_bfloat16* Phi = sm + 2 * 128 * AST;
    __nv_bfloat16* Plo = sm + 2 * 128 * AST + 64 * AST;
    float* sbias = (float*)(sm + 2 * 128 * AST + 2 * 64 * AST);

    int t = threadIdx.x;
    int row0 = blockIdx.x * 128;
    if (t < 64) sbias[t] = bp[t];

    int wid = t >> 5, lane = t & 31;
    int g = lane >> 2, tq = lane & 3;
    int r0 = wid * 16;

    int aoff = (r0 + (lane & 15)) * AST + (lane >> 4) * 8;
    uint32_t aHiB = smem_u32(Hhi) + aoff * 2;
    uint32_t aLoB = smem_u32(Hlo) + aoff * 2;
    int bcol = ((lane >> 4) << 3) + (lane & 7);
    int bkh = ((lane >> 3) & 1) * 8;
    uint32_t bHiB = smem_u32(Phi) + (bcol * AST + bkh) * 2;
    uint32_t bLoB = smem_u32(Plo) + (bcol * AST + bkh) * 2;

    float acc[8][4];
#pragma unroll
    for (int nt = 0; nt < 8; nt++)
#pragma unroll
        for (int j = 0; j < 4; j++) acc[nt][j] = 0.f;

    for (int kc = 0; kc < 256; kc += 64) {
        __syncthreads();
#pragma unroll
        for (int i = 0; i < 4; i++) {
            int u = t + i * 256;
            int r = u >> 3, qd = u & 7;
            int rg = row0 + r;
            uint4 vh = make_uint4(0, 0, 0, 0), vl = make_uint4(0, 0, 0, 0);
            if (rg < NN) {
                vh = *(const uint4*)(g_hhi + (size_t)rg * 256 + kc + qd * 8);
                vl = *(const uint4*)(g_hlo + (size_t)rg * 256 + kc + qd * 8);
            }
            *(uint4*)(Hhi + r * AST + qd * 8) = vh;
            *(uint4*)(Hlo + r * AST + qd * 8) = vl;
        }
#pragma unroll
        for (int i = 0; i < 4; i++) {
            int u = t + i * 256;
            int r = u >> 4, qd = u & 15;
            float4 w4 = *(const float4*)(Wp + (size_t)r * 256 + kc + qd * 4);
            __nv_bfloat162 h0, l0, h1, l1;
            split2(w4.x, w4.y, h0, l0);
            split2(w4.z, w4.w, h1, l1);
            int so = r * AST + qd * 4;
            *(__nv_bfloat162*)(Phi + so) = h0;  *(__nv_bfloat162*)(Phi + so + 2) = h1;
            *(__nv_bfloat162*)(Plo + so) = l0;  *(__nv_bfloat162*)(Plo + so + 2) = l1;
        }
        __syncthreads();

#pragma unroll
        for (int ks = 0; ks < 4; ks++) {
            uint32_t kbB = ks * 32;
            uint32_t ahi[4], alo[4];
            LDMX4(ahi, aHiB + kbB);
            LDMX4(alo, aLoB + kbB);
#pragma unroll
            for (int ntg = 0; ntg < 4; ntg++) {
                uint32_t cgB = (uint32_t)(ntg * 16 * AST * 2);
                uint32_t bh[4], bl[4];
                LDMX4(bh, bHiB + cgB + kbB);
                LDMX4(bl, bLoB + cgB + kbB);
                mma16816(acc[2 * ntg],     ahi, bh);
                mma16816(acc[2 * ntg + 1], ahi, bh + 2);
                mma16816(acc[2 * ntg],     ahi, bl);
                mma16816(acc[2 * ntg + 1], ahi, bl + 2);
                mma16816(acc[2 * ntg],     alo, bh);
                mma16816(acc[2 * ntg + 1], alo, bh + 2);
            }
        }
    }

    int rA = row0 + r0 + g;
    int rB = rA + 8;
#pragma unroll
    for (int nt = 0; nt < 8; nt++) {
        int lc = nt * 8 + tq * 2;
        float b0 = sbias[lc], b1 = sbias[lc + 1];
        if (rA < NN) {
            float2 xv = *(const float2*)(x + (size_t)rA * 64 + lc);
            *(float2*)(out + (size_t)rA * 64 + lc) =
                make_float2(fmaxf(acc[nt][0] + b0 + xv.x, 0.f), fmaxf(acc[nt][1] + b1 + xv.y, 0.f));
        }
        if (rB < NN) {
            float2 xv = *(const float2*)(x + (size_t)rB * 64 + lc);
            *(float2*)(out + (size_t)rB * 64 + lc) =
                make_float2(fmaxf(acc[nt][2] + b0 + xv.x, 0.f), fmaxf(acc[nt][3] + b1 + xv.y, 0.f));
        }
    }
}

// ============================================================================
extern "C" void kernel_launch(void* const* d_in, const int* in_sizes, int n_in,
                              void* d_out, int out_size)
{
    const float* x     = (const float*)d_in[0];
    const int*   ei    = (const int*)d_in[1];
    const float* Wq    = (const float*)d_in[2];
    const float* bq    = (const float*)d_in[3];
    const float* Wk    = (const float*)d_in[4];
    const float* bk    = (const float*)d_in[5];
    const float* Wv    = (const float*)d_in[6];
    const float* bv    = (const float*)d_in[7];
    const float* Wsk   = (const float*)d_in[8];
    const float* bsk   = (const float*)d_in[9];
    const float* Wbeta = (const float*)d_in[10];
    const float* lng   = (const float*)d_in[11];
    const float* lnb   = (const float*)d_in[12];
    const float* Wp    = (const float*)d_in[13];
    const float* bp    = (const float*)d_in[14];
    float* out = (float*)d_out;

    static int attr_set = 0;
    if (!attr_set) {
        cudaFuncSetAttribute(gemm_qkvs_mma,
                             cudaFuncAttributeMaxDynamicSharedMemorySize, QKV_SMEM_BYTES);
        cudaFuncSetAttribute(gemm_proj_mma,
                             cudaFuncAttributeMaxDynamicSharedMemorySize, PROJ_SMEM_BYTES);
        attr_set = 1;
    }

    void* dcp = nullptr;
    cudaGetSymbolAddress(&dcp, g_degcur);
    cudaMemsetAsync(dcp, 0, 2 * NN * sizeof(int));

    hist_kernel<<<2500, 256>>>(ei);
    scan_kernel<<<1, 1024>>>();
    scatter_kernel<<<2500, 256>>>(ei);
    gemm_qkvs_mma<<<dim3(8, 391), 256, QKV_SMEM_BYTES>>>(x, Wq, bq, Wk, bk, Wv, bv, Wsk, bsk);
    attn_kernel<<<6250, 256>>>(Wbeta, lng, lnb);
    gemm_proj_mma<<<391, 256, PROJ_SMEM_BYTES>>>(x, Wp, bp, out);
}